// round 1
// baseline (speedup 1.0000x reference)
#include <cuda_runtime.h>
#include <cuda_bf16.h>
#include <math.h>

// Problem constants
#define BB 2
#define SS 4096
#define DD 768
#define HH 12
#define LL 4
#define WW 128
#define DFF 3072
#define DH 64
#define MM (BB*SS)          // 8192 rows
#define NC (SS/WW)          // 32 chunks

#define NEG_BIG (-1e30f)

// ---------------- scratch buffers (no allocation allowed) ----------------
__device__ float g_x [MM*DD];
__device__ float g_q [MM*DD];
__device__ float g_k [MM*DD];
__device__ float g_v [MM*DD];
__device__ float g_h1[MM*DFF];
__device__ float g_h2[MM*DD];

// ---------------- SGEMM: C = A(MxK) @ B(KxN) + bias, optional ReLU ----------------
// 128x128 block tile, BK=16, 256 threads, 8x8 per thread.
#define BM 128
#define BN 128
#define BK 16

template<bool RELU>
__global__ __launch_bounds__(256) void sgemm_bias(
    const float* __restrict__ A, const float* __restrict__ Bm,
    const float* __restrict__ bias, float* __restrict__ C,
    int M, int N, int K)
{
    __shared__ __align__(16) float As[BK][BM + 4];
    __shared__ __align__(16) float Bs[BK][BN];

    const int tid = threadIdx.x;
    const int bx = blockIdx.x;   // N tiles
    const int by = blockIdx.y;   // M tiles
    const int tx = tid & 15;
    const int ty = tid >> 4;

    const float* Ablk = A + (size_t)by * BM * K;
    const float* Bblk = Bm + (size_t)bx * BN;

    const int arow = tid >> 2;       // 0..63
    const int acol4 = tid & 3;       // 0..3
    const int brow = tid >> 5;       // 0..7
    const int bcol4 = tid & 31;      // 0..31

    float acc[8][8];
    #pragma unroll
    for (int i = 0; i < 8; i++)
        #pragma unroll
        for (int j = 0; j < 8; j++) acc[i][j] = 0.f;

    for (int k0 = 0; k0 < K; k0 += BK) {
        // Load A tile (transposed into smem)
        #pragma unroll
        for (int r = 0; r < 2; r++) {
            int row = arow + r * 64;
            float4 a4 = *(const float4*)(Ablk + (size_t)row * K + k0 + acol4 * 4);
            As[acol4*4 + 0][row] = a4.x;
            As[acol4*4 + 1][row] = a4.y;
            As[acol4*4 + 2][row] = a4.z;
            As[acol4*4 + 3][row] = a4.w;
        }
        // Load B tile
        #pragma unroll
        for (int r = 0; r < 2; r++) {
            int row = brow + r * 8;
            *(float4*)(&Bs[row][bcol4*4]) =
                *(const float4*)(Bblk + (size_t)(k0 + row) * N + bcol4 * 4);
        }
        __syncthreads();

        #pragma unroll
        for (int kk = 0; kk < BK; kk++) {
            float4 a0 = *(const float4*)(&As[kk][ty*4]);
            float4 a1 = *(const float4*)(&As[kk][ty*4 + 64]);
            float4 b0 = *(const float4*)(&Bs[kk][tx*4]);
            float4 b1 = *(const float4*)(&Bs[kk][tx*4 + 64]);
            float ra[8] = {a0.x, a0.y, a0.z, a0.w, a1.x, a1.y, a1.z, a1.w};
            float rb[8] = {b0.x, b0.y, b0.z, b0.w, b1.x, b1.y, b1.z, b1.w};
            #pragma unroll
            for (int i = 0; i < 8; i++)
                #pragma unroll
                for (int j = 0; j < 8; j++)
                    acc[i][j] += ra[i] * rb[j];
        }
        __syncthreads();
    }

    // Epilogue: bias (+ReLU)
    #pragma unroll
    for (int i = 0; i < 8; i++) {
        int row = by * BM + ((i < 4) ? (ty*4 + i) : (64 + ty*4 + i - 4));
        #pragma unroll
        for (int half = 0; half < 2; half++) {
            int col = bx * BN + ((half == 0) ? (tx*4) : (64 + tx*4));
            float4 o;
            o.x = acc[i][half*4 + 0] + bias[col + 0];
            o.y = acc[i][half*4 + 1] + bias[col + 1];
            o.z = acc[i][half*4 + 2] + bias[col + 2];
            o.w = acc[i][half*4 + 3] + bias[col + 3];
            if (RELU) {
                o.x = fmaxf(o.x, 0.f); o.y = fmaxf(o.y, 0.f);
                o.z = fmaxf(o.z, 0.f); o.w = fmaxf(o.w, 0.f);
            }
            *(float4*)(C + (size_t)row * N + col) = o;
        }
    }
}

// ---------------- Band (sliding window) attention ----------------
// Grid: (NC, HH, BB). 128 threads, one query row per thread.
// Flash-style over 3 key tiles of 128; scores staged in padded smem.
// Writes xout = xin + attn_out (residual fused).
__global__ __launch_bounds__(128) void band_attn_kernel(
    const float* __restrict__ q, const float* __restrict__ k,
    const float* __restrict__ v, const float* __restrict__ xin,
    float* __restrict__ xout)
{
    extern __shared__ float smem[];
    float* ks = smem;                 // 128*64
    float* vs = smem + 128*64;        // 128*64
    float* sc = smem + 2*128*64;      // 128*129 (padded)

    const int c  = blockIdx.x;
    const int h  = blockIdx.y;
    const int b  = blockIdx.z;
    const int qi = threadIdx.x;

    const int srow = c * WW + qi;
    const size_t qbase = ((size_t)(b * SS + srow)) * DD + h * DH;

    float qr[DH];
    #pragma unroll
    for (int d4 = 0; d4 < DH/4; d4++) {
        float4 t4 = *(const float4*)(q + qbase + d4*4);
        qr[d4*4+0] = t4.x * 0.125f;
        qr[d4*4+1] = t4.y * 0.125f;
        qr[d4*4+2] = t4.z * 0.125f;
        qr[d4*4+3] = t4.w * 0.125f;
    }

    float m = NEG_BIG, l = 0.f;
    float acc[DH];
    #pragma unroll
    for (int d = 0; d < DH; d++) acc[d] = 0.f;

    for (int t = 0; t < 3; t++) {
        // cooperative tile load: thread qi loads key row (t*128 + qi)
        int ki_load = t * 128 + qi;
        int jg = c * WW + ki_load - WW;
        bool inr = (jg >= 0) && (jg < SS);
        size_t kb = ((size_t)(b * SS + (inr ? jg : 0))) * DD + h * DH;
        #pragma unroll
        for (int d4 = 0; d4 < DH/4; d4++) {
            float4 k4 = inr ? *(const float4*)(k + kb + d4*4) : make_float4(0,0,0,0);
            float4 v4 = inr ? *(const float4*)(v + kb + d4*4) : make_float4(0,0,0,0);
            *(float4*)(ks + qi*DH + d4*4) = k4;
            *(float4*)(vs + qi*DH + d4*4) = v4;
        }
        __syncthreads();

        // scores for this tile
        float tmax = NEG_BIG;
        for (int j = 0; j < 128; j++) {
            int ki = t * 128 + j;
            int jgj = c * WW + ki - WW;
            const float* kr = ks + j * DH;
            float s0 = 0.f, s1 = 0.f, s2 = 0.f, s3 = 0.f;
            #pragma unroll
            for (int d = 0; d < DH; d += 4) {
                s0 += qr[d+0] * kr[d+0];
                s1 += qr[d+1] * kr[d+1];
                s2 += qr[d+2] * kr[d+2];
                s3 += qr[d+3] * kr[d+3];
            }
            float s = (s0 + s1) + (s2 + s3);
            bool valid = (ki >= qi) && (ki <= qi + 2*WW) && (jgj >= 0) && (jgj < SS);
            s = valid ? s : NEG_BIG;
            sc[qi * 129 + j] = s;
            tmax = fmaxf(tmax, s);
        }

        if (tmax > -1e29f) {
            float mnew = fmaxf(m, tmax);
            float scale = __expf(m - mnew);
            l *= scale;
            #pragma unroll
            for (int d = 0; d < DH; d++) acc[d] *= scale;
            for (int j = 0; j < 128; j++) {
                float p = __expf(sc[qi * 129 + j] - mnew);
                l += p;
                const float* vr = vs + j * DH;
                #pragma unroll
                for (int d = 0; d < DH; d++) acc[d] += p * vr[d];
            }
            m = mnew;
        }
        __syncthreads();
    }

    float inv = 1.0f / l;
    #pragma unroll
    for (int d4 = 0; d4 < DH/4; d4++) {
        float4 xi = *(const float4*)(xin + qbase + d4*4);
        float4 o;
        o.x = xi.x + acc[d4*4+0] * inv;
        o.y = xi.y + acc[d4*4+1] * inv;
        o.z = xi.z + acc[d4*4+2] * inv;
        o.w = xi.w + acc[d4*4+3] * inv;
        *(float4*)(xout + qbase + d4*4) = o;
    }
}

// ---------------- fused add + LayerNorm ----------------
// out[row] = LN(x[row] + h[row]) * g + b ; h optional. 256 threads, 3 elems/thread.
__device__ __forceinline__ float block_sum_256(float v, float* red) {
    int lane = threadIdx.x & 31;
    #pragma unroll
    for (int o = 16; o > 0; o >>= 1) v += __shfl_xor_sync(0xffffffffu, v, o);
    if (lane == 0) red[threadIdx.x >> 5] = v;
    __syncthreads();
    float r = (threadIdx.x < 8) ? red[threadIdx.x] : 0.f;
    if ((threadIdx.x >> 5) == 0) {
        #pragma unroll
        for (int o = 16; o > 0; o >>= 1) r += __shfl_xor_sync(0xffffffffu, r, o);
        if (lane == 0) red[0] = r;
    }
    __syncthreads();
    r = red[0];
    __syncthreads();
    return r;
}

__global__ __launch_bounds__(256) void add_ln_kernel(
    const float* __restrict__ x, const float* __restrict__ hh,
    const float* __restrict__ g, const float* __restrict__ bta,
    float* __restrict__ out, int hasH)
{
    __shared__ float red[8];
    const int row = blockIdx.x;
    const size_t base = (size_t)row * DD;
    const int t = threadIdx.x;

    float vals[3];
    float s = 0.f;
    #pragma unroll
    for (int i = 0; i < 3; i++) {
        int idx = t + i * 256;
        float vv = x[base + idx];
        if (hasH) vv += hh[base + idx];
        vals[i] = vv;
        s += vv;
    }
    float total = block_sum_256(s, red);
    float mu = total * (1.0f / DD);

    float vsum = 0.f;
    #pragma unroll
    for (int i = 0; i < 3; i++) {
        float d = vals[i] - mu;
        vsum += d * d;
    }
    float vtot = block_sum_256(vsum, red);
    float rstd = rsqrtf(vtot * (1.0f / DD) + 1e-6f);

    #pragma unroll
    for (int i = 0; i < 3; i++) {
        int idx = t + i * 256;
        out[base + idx] = (vals[i] - mu) * rstd * g[idx] + bta[idx];
    }
}

// ---------------- launcher ----------------
extern "C" void kernel_launch(void* const* d_in, const int* in_sizes, int n_in,
                              void* d_out, int out_size)
{
    const float* src   = (const float*)d_in[0];
    const float* Wq    = (const float*)d_in[1];
    const float* bq    = (const float*)d_in[2];
    const float* Wk    = (const float*)d_in[3];
    const float* bk    = (const float*)d_in[4];
    const float* Wv    = (const float*)d_in[5];
    const float* bv    = (const float*)d_in[6];
    const float* W1    = (const float*)d_in[7];
    const float* b1    = (const float*)d_in[8];
    const float* W2    = (const float*)d_in[9];
    const float* b2    = (const float*)d_in[10];
    const float* ln2_g = (const float*)d_in[11];
    const float* ln2_b = (const float*)d_in[12];
    const float* lnf_g = (const float*)d_in[13];
    const float* lnf_b = (const float*)d_in[14];

    float *x, *q, *k, *v, *h1, *h2;
    cudaGetSymbolAddress((void**)&x,  g_x);
    cudaGetSymbolAddress((void**)&q,  g_q);
    cudaGetSymbolAddress((void**)&k,  g_k);
    cudaGetSymbolAddress((void**)&v,  g_v);
    cudaGetSymbolAddress((void**)&h1, g_h1);
    cudaGetSymbolAddress((void**)&h2, g_h2);

    const size_t attn_smem = (size_t)(2 * 128 * 64 + 128 * 129) * sizeof(float); // ~128.5KB
    cudaFuncSetAttribute(band_attn_kernel,
                         cudaFuncAttributeMaxDynamicSharedMemorySize, (int)attn_smem);

    dim3 gD(DD / BN, MM / BM);    // (6, 64)
    dim3 gF(DFF / BN, MM / BM);   // (24, 64)
    dim3 gA(NC, HH, BB);          // (32, 12, 2)

    for (int i = 0; i < LL; i++) {
        const float* xin = (i == 0) ? src : x;
        const float* wq = Wq + (size_t)i * DD * DD;
        const float* wk = Wk + (size_t)i * DD * DD;
        const float* wv = Wv + (size_t)i * DD * DD;

        sgemm_bias<false><<<gD, 256>>>(xin, wq, bq + i * DD, q, MM, DD, DD);
        sgemm_bias<false><<<gD, 256>>>(xin, wk, bk + i * DD, k, MM, DD, DD);
        sgemm_bias<false><<<gD, 256>>>(xin, wv, bv + i * DD, v, MM, DD, DD);

        band_attn_kernel<<<gA, 128, attn_smem>>>(q, k, v, xin, x);

        sgemm_bias<true ><<<gF, 256>>>(x, W1 + (size_t)i * DD * DFF, b1 + i * DFF, h1, MM, DFF, DD);
        sgemm_bias<false><<<gD, 256>>>(h1, W2 + (size_t)i * DFF * DD, b2 + i * DD, h2, MM, DD, DFF);

        add_ln_kernel<<<MM, 256>>>(x, h2, ln2_g + i * DD, ln2_b + i * DD, x, 1);
    }

    add_ln_kernel<<<MM, 256>>>(x, nullptr, lnf_g, lnf_b, (float*)d_out, 0);
}

// round 3
// speedup vs baseline: 1.6285x; 1.6285x over previous
#include <cuda_runtime.h>
#include <cuda_bf16.h>
#include <math.h>
#include <stdint.h>

// Problem constants
#define BB 2
#define SS 4096
#define DD 768
#define HH 12
#define LL 4
#define WW 128
#define DFF 3072
#define DH 64
#define MM (BB*SS)          // 8192 rows
#define NC (SS/WW)          // 32 chunks

#define NEG_BIG (-1e30f)

// ---------------- scratch buffers (no allocation allowed) ----------------
__device__ float g_x [MM*DD];
__device__ float g_q [MM*DD];
__device__ float g_k [MM*DD];
__device__ float g_v [MM*DD];
__device__ float g_h1[MM*DFF];
__device__ float g_h2[MM*DD];

// ---------------- helpers ----------------
__device__ __forceinline__ uint32_t tf32_rna(float f) {
    uint32_t u;
    asm("cvt.rna.tf32.f32 %0, %1;" : "=r"(u) : "f"(f));
    return u;
}
__device__ __forceinline__ void mma16n8k8(float* c, const uint32_t* a, const uint32_t* b) {
    asm volatile(
        "mma.sync.aligned.m16n8k8.row.col.f32.tf32.tf32.f32 "
        "{%0,%1,%2,%3}, {%4,%5,%6,%7}, {%8,%9}, {%0,%1,%2,%3};"
        : "+f"(c[0]), "+f"(c[1]), "+f"(c[2]), "+f"(c[3])
        : "r"(a[0]), "r"(a[1]), "r"(a[2]), "r"(a[3]), "r"(b[0]), "r"(b[1]));
}

// ---------------- tf32 mma.sync GEMM: C = A(MxK) @ B(KxN) + bias (+ReLU) ----------------
// 128x128 tile / CTA, 8 warps, warp tile 64x32, K-chunk 32, double-buffered smem.
#define KB 32
#define A_PAD 36     // bank = (4*row + k) % 32 : conflict-free A frag loads
#define B_PAD 136    // bank = (8*k + n) % 32 : conflict-free B frag loads
#define A_BUF (128*A_PAD)
#define B_BUF (KB*B_PAD)
#define GEMM_SMEM ((2*A_BUF + 2*B_BUF)*4)

template<bool RELU>
__global__ __launch_bounds__(256, 2) void gemm_mma(
    const float* __restrict__ A, const float* __restrict__ Bm,
    const float* __restrict__ bias, float* __restrict__ C,
    int M, int N, int K)
{
    extern __shared__ float sm[];
    float* AsBase = sm;                 // 2 x 128 x A_PAD
    float* BsBase = sm + 2*A_BUF;       // 2 x KB x B_PAD

    const int tid  = threadIdx.x;
    const int lane = tid & 31;
    const int wid  = tid >> 5;
    const int wm   = wid & 1;           // 2 m-warps of 64 rows
    const int wn   = wid >> 1;          // 4 n-warps of 32 cols
    const int tn = blockIdx.x, tm = blockIdx.y;

    // loader mapping
    const int arow = tid >> 1;                 // 0..127
    const int acol = (tid & 1) * 16;           // 0 or 16
    const int brow = tid >> 3;                 // 0..31 (k)
    const int bcol = (tid & 7) * 16;           // 0..112 (n)
    const float* Aptr = A  + (size_t)(tm * 128 + arow) * K + acol;
    const float* Bptr = Bm + (size_t)brow * N + tn * 128 + bcol;

    float acc[4][4][4];
    #pragma unroll
    for (int i = 0; i < 4; i++)
        #pragma unroll
        for (int j = 0; j < 4; j++)
            #pragma unroll
            for (int t = 0; t < 4; t++) acc[i][j][t] = 0.f;

    const int r4 = lane >> 2;   // 0..7
    const int t4 = lane & 3;    // 0..3
    const int mbase = wm * 64;
    const int nbase = wn * 32;

    const int NCH = K / KB;
    for (int c = 0; c < NCH; c++) {
        float* as = AsBase + (c & 1) * A_BUF;
        float* bs = BsBase + (c & 1) * B_BUF;
        const float* ap = Aptr + c * KB;
        const float* bp = Bptr + (size_t)c * KB * N;
        // stage A[128 x 32] as [m][k], B[32 x 128] as [k][n], cvt to tf32
        #pragma unroll
        for (int i = 0; i < 4; i++) {
            float4 a4 = *(const float4*)(ap + i * 4);
            float4 b4 = *(const float4*)(bp + i * 4);
            float* ad = as + arow * A_PAD + acol + i * 4;
            float* bd = bs + brow * B_PAD + bcol + i * 4;
            ad[0] = __uint_as_float(tf32_rna(a4.x));
            ad[1] = __uint_as_float(tf32_rna(a4.y));
            ad[2] = __uint_as_float(tf32_rna(a4.z));
            ad[3] = __uint_as_float(tf32_rna(a4.w));
            bd[0] = __uint_as_float(tf32_rna(b4.x));
            bd[1] = __uint_as_float(tf32_rna(b4.y));
            bd[2] = __uint_as_float(tf32_rna(b4.z));
            bd[3] = __uint_as_float(tf32_rna(b4.w));
        }
        __syncthreads();   // single sync: buffer s is re-written 2 iters later, after these reads

        #pragma unroll
        for (int ks = 0; ks < 4; ks++) {
            const int k0 = ks * 8;
            uint32_t af[4][4], bf[4][2];
            #pragma unroll
            for (int mi = 0; mi < 4; mi++) {
                const float* ar = as + (mbase + mi * 16 + r4) * A_PAD + k0 + t4;
                af[mi][0] = __float_as_uint(ar[0]);
                af[mi][1] = __float_as_uint(ar[8 * A_PAD]);
                af[mi][2] = __float_as_uint(ar[4]);
                af[mi][3] = __float_as_uint(ar[8 * A_PAD + 4]);
            }
            #pragma unroll
            for (int ni = 0; ni < 4; ni++) {
                const float* br = bs + (k0 + t4) * B_PAD + nbase + ni * 8 + r4;
                bf[ni][0] = __float_as_uint(br[0]);
                bf[ni][1] = __float_as_uint(br[4 * B_PAD]);
            }
            #pragma unroll
            for (int mi = 0; mi < 4; mi++)
                #pragma unroll
                for (int ni = 0; ni < 4; ni++)
                    mma16n8k8(acc[mi][ni], af[mi], bf[ni]);
        }
    }

    // epilogue: bias (+ReLU), float2 stores
    #pragma unroll
    for (int mi = 0; mi < 4; mi++) {
        const int row0 = tm * 128 + mbase + mi * 16 + r4;
        #pragma unroll
        for (int ni = 0; ni < 4; ni++) {
            const int col = tn * 128 + nbase + ni * 8 + t4 * 2;
            const float b0 = bias[col], b1 = bias[col + 1];
            float2 v0, v1;
            v0.x = acc[mi][ni][0] + b0; v0.y = acc[mi][ni][1] + b1;
            v1.x = acc[mi][ni][2] + b0; v1.y = acc[mi][ni][3] + b1;
            if (RELU) {
                v0.x = fmaxf(v0.x, 0.f); v0.y = fmaxf(v0.y, 0.f);
                v1.x = fmaxf(v1.x, 0.f); v1.y = fmaxf(v1.y, 0.f);
            }
            *(float2*)(C + (size_t)row0 * N + col)       = v0;
            *(float2*)(C + (size_t)(row0 + 8) * N + col) = v1;
        }
    }
}

// ---------------- Band (sliding window) attention ----------------
__global__ __launch_bounds__(128) void band_attn_kernel(
    const float* __restrict__ q, const float* __restrict__ k,
    const float* __restrict__ v, const float* __restrict__ xin,
    float* __restrict__ xout)
{
    extern __shared__ float smem[];
    float* ks = smem;                 // 128*64
    float* vs = smem + 128*64;        // 128*64
    float* sc = smem + 2*128*64;      // 128*129 (padded)

    const int c  = blockIdx.x;
    const int h  = blockIdx.y;
    const int b  = blockIdx.z;
    const int qi = threadIdx.x;

    const int srow = c * WW + qi;
    const size_t qbase = ((size_t)(b * SS + srow)) * DD + h * DH;

    float qr[DH];
    #pragma unroll
    for (int d4 = 0; d4 < DH/4; d4++) {
        float4 t4 = *(const float4*)(q + qbase + d4*4);
        qr[d4*4+0] = t4.x * 0.125f;
        qr[d4*4+1] = t4.y * 0.125f;
        qr[d4*4+2] = t4.z * 0.125f;
        qr[d4*4+3] = t4.w * 0.125f;
    }

    float m = NEG_BIG, l = 0.f;
    float acc[DH];
    #pragma unroll
    for (int d = 0; d < DH; d++) acc[d] = 0.f;

    for (int t = 0; t < 3; t++) {
        int ki_load = t * 128 + qi;
        int jg = c * WW + ki_load - WW;
        bool inr = (jg >= 0) && (jg < SS);
        size_t kb = ((size_t)(b * SS + (inr ? jg : 0))) * DD + h * DH;
        #pragma unroll
        for (int d4 = 0; d4 < DH/4; d4++) {
            float4 k4 = inr ? *(const float4*)(k + kb + d4*4) : make_float4(0,0,0,0);
            float4 v4 = inr ? *(const float4*)(v + kb + d4*4) : make_float4(0,0,0,0);
            *(float4*)(ks + qi*DH + d4*4) = k4;
            *(float4*)(vs + qi*DH + d4*4) = v4;
        }
        __syncthreads();

        float tmax = NEG_BIG;
        for (int j = 0; j < 128; j++) {
            int ki = t * 128 + j;
            int jgj = c * WW + ki - WW;
            const float* kr = ks + j * DH;
            float s0 = 0.f, s1 = 0.f, s2 = 0.f, s3 = 0.f;
            #pragma unroll
            for (int d = 0; d < DH; d += 4) {
                s0 += qr[d+0] * kr[d+0];
                s1 += qr[d+1] * kr[d+1];
                s2 += qr[d+2] * kr[d+2];
                s3 += qr[d+3] * kr[d+3];
            }
            float s = (s0 + s1) + (s2 + s3);
            bool valid = (ki >= qi) && (ki <= qi + 2*WW) && (jgj >= 0) && (jgj < SS);
            s = valid ? s : NEG_BIG;
            sc[qi * 129 + j] = s;
            tmax = fmaxf(tmax, s);
        }

        if (tmax > -1e29f) {
            float mnew = fmaxf(m, tmax);
            float scale = __expf(m - mnew);
            l *= scale;
            #pragma unroll
            for (int d = 0; d < DH; d++) acc[d] *= scale;
            for (int j = 0; j < 128; j++) {
                float p = __expf(sc[qi * 129 + j] - mnew);
                l += p;
                const float* vr = vs + j * DH;
                #pragma unroll
                for (int d = 0; d < DH; d++) acc[d] += p * vr[d];
            }
            m = mnew;
        }
        __syncthreads();
    }

    float inv = 1.0f / l;
    #pragma unroll
    for (int d4 = 0; d4 < DH/4; d4++) {
        float4 xi = *(const float4*)(xin + qbase + d4*4);
        float4 o;
        o.x = xi.x + acc[d4*4+0] * inv;
        o.y = xi.y + acc[d4*4+1] * inv;
        o.z = xi.z + acc[d4*4+2] * inv;
        o.w = xi.w + acc[d4*4+3] * inv;
        *(float4*)(xout + qbase + d4*4) = o;
    }
}

// ---------------- fused add + LayerNorm ----------------
__device__ __forceinline__ float block_sum_256(float v, float* red) {
    int lane = threadIdx.x & 31;
    #pragma unroll
    for (int o = 16; o > 0; o >>= 1) v += __shfl_xor_sync(0xffffffffu, v, o);
    if (lane == 0) red[threadIdx.x >> 5] = v;
    __syncthreads();
    float r = (threadIdx.x < 8) ? red[threadIdx.x] : 0.f;
    if ((threadIdx.x >> 5) == 0) {
        #pragma unroll
        for (int o = 16; o > 0; o >>= 1) r += __shfl_xor_sync(0xffffffffu, r, o);
        if (lane == 0) red[0] = r;
    }
    __syncthreads();
    r = red[0];
    __syncthreads();
    return r;
}

__global__ __launch_bounds__(256) void add_ln_kernel(
    const float* __restrict__ x, const float* __restrict__ hh,
    const float* __restrict__ g, const float* __restrict__ bta,
    float* __restrict__ out, int hasH)
{
    __shared__ float red[8];
    const int row = blockIdx.x;
    const size_t base = (size_t)row * DD;
    const int t = threadIdx.x;

    float vals[3];
    float s = 0.f;
    #pragma unroll
    for (int i = 0; i < 3; i++) {
        int idx = t + i * 256;
        float vv = x[base + idx];
        if (hasH) vv += hh[base + idx];
        vals[i] = vv;
        s += vv;
    }
    float total = block_sum_256(s, red);
    float mu = total * (1.0f / DD);

    float vsum = 0.f;
    #pragma unroll
    for (int i = 0; i < 3; i++) {
        float d = vals[i] - mu;
        vsum += d * d;
    }
    float vtot = block_sum_256(vsum, red);
    float rstd = rsqrtf(vtot * (1.0f / DD) + 1e-6f);

    #pragma unroll
    for (int i = 0; i < 3; i++) {
        int idx = t + i * 256;
        out[base + idx] = (vals[i] - mu) * rstd * g[idx] + bta[idx];
    }
}

// ---------------- launcher ----------------
extern "C" void kernel_launch(void* const* d_in, const int* in_sizes, int n_in,
                              void* d_out, int out_size)
{
    const float* src   = (const float*)d_in[0];
    const float* Wq    = (const float*)d_in[1];
    const float* bq    = (const float*)d_in[2];
    const float* Wk    = (const float*)d_in[3];
    const float* bk    = (const float*)d_in[4];
    const float* Wv    = (const float*)d_in[5];
    const float* bv    = (const float*)d_in[6];
    const float* W1    = (const float*)d_in[7];
    const float* b1    = (const float*)d_in[8];
    const float* W2    = (const float*)d_in[9];
    const float* b2    = (const float*)d_in[10];
    const float* ln2_g = (const float*)d_in[11];
    const float* ln2_b = (const float*)d_in[12];
    const float* lnf_g = (const float*)d_in[13];
    const float* lnf_b = (const float*)d_in[14];

    float *x, *q, *k, *v, *h1, *h2;
    cudaGetSymbolAddress((void**)&x,  g_x);
    cudaGetSymbolAddress((void**)&q,  g_q);
    cudaGetSymbolAddress((void**)&k,  g_k);
    cudaGetSymbolAddress((void**)&v,  g_v);
    cudaGetSymbolAddress((void**)&h1, g_h1);
    cudaGetSymbolAddress((void**)&h2, g_h2);

    const size_t attn_smem = (size_t)(2 * 128 * 64 + 128 * 129) * sizeof(float);
    cudaFuncSetAttribute(band_attn_kernel,
                         cudaFuncAttributeMaxDynamicSharedMemorySize, (int)attn_smem);
    cudaFuncSetAttribute(gemm_mma<false>,
                         cudaFuncAttributeMaxDynamicSharedMemorySize, GEMM_SMEM);
    cudaFuncSetAttribute(gemm_mma<true>,
                         cudaFuncAttributeMaxDynamicSharedMemorySize, GEMM_SMEM);

    dim3 gD(DD / 128, MM / 128);    // (6, 64)
    dim3 gF(DFF / 128, MM / 128);   // (24, 64)
    dim3 gA(NC, HH, BB);            // (32, 12, 2)

    for (int i = 0; i < LL; i++) {
        const float* xin = (i == 0) ? src : x;

        gemm_mma<false><<<gD, 256, GEMM_SMEM>>>(xin, Wq + (size_t)i*DD*DD, bq + i*DD, q, MM, DD, DD);
        gemm_mma<false><<<gD, 256, GEMM_SMEM>>>(xin, Wk + (size_t)i*DD*DD, bk + i*DD, k, MM, DD, DD);
        gemm_mma<false><<<gD, 256, GEMM_SMEM>>>(xin, Wv + (size_t)i*DD*DD, bv + i*DD, v, MM, DD, DD);

        band_attn_kernel<<<gA, 128, attn_smem>>>(q, k, v, xin, x);

        gemm_mma<true ><<<gF, 256, GEMM_SMEM>>>(x,  W1 + (size_t)i*DD*DFF, b1 + i*DFF, h1, MM, DFF, DD);
        gemm_mma<false><<<gD, 256, GEMM_SMEM>>>(h1, W2 + (size_t)i*DFF*DD, b2 + i*DD,  h2, MM, DD, DFF);

        add_ln_kernel<<<MM, 256>>>(x, h2, ln2_g + i*DD, ln2_b + i*DD, x, 1);
    }

    add_ln_kernel<<<MM, 256>>>(x, nullptr, lnf_g, lnf_b, (float*)d_out, 0);
}

// round 4
// speedup vs baseline: 1.7943x; 1.1018x over previous
#include <cuda_runtime.h>
#include <cuda_bf16.h>
#include <math.h>
#include <stdint.h>

// Problem constants
#define BB 2
#define SS 4096
#define DD 768
#define HH 12
#define LL 4
#define WW 128
#define DFF 3072
#define DH 64
#define MM (BB*SS)          // 8192 rows
#define NC (SS/WW)          // 32 chunks

#define NEG_BIG (-1e30f)

// ---------------- scratch buffers ----------------
__device__ float g_x [MM*DD];
__device__ float g_q [MM*DD];
__device__ float g_k [MM*DD];
__device__ float g_v [MM*DD];
__device__ float g_h1[MM*DFF];
__device__ float g_h2[MM*DD];
__device__ float g_xr[MM*DD];            // tf32-rounded activations
__device__ float g_wqr[LL*DD*DD];        // tf32-rounded weights
__device__ float g_wkr[LL*DD*DD];
__device__ float g_wvr[LL*DD*DD];
__device__ float g_w1r[LL*DD*DFF];
__device__ float g_w2r[LL*DFF*DD];

// ---------------- helpers ----------------
__device__ __forceinline__ uint32_t tf32_rna(float f) {
    uint32_t u;
    asm("cvt.rna.tf32.f32 %0, %1;" : "=r"(u) : "f"(f));
    return u;
}
__device__ __forceinline__ uint32_t smem_u32(const void* p) {
    uint32_t a;
    asm("{ .reg .u64 t; cvta.to.shared.u64 t, %1; cvt.u32.u64 %0, t; }"
        : "=r"(a) : "l"(p));
    return a;
}
__device__ __forceinline__ void cp16(uint32_t s, const void* g) {
    asm volatile("cp.async.cg.shared.global [%0], [%1], 16;" :: "r"(s), "l"(g));
}
__device__ __forceinline__ void mma16n8k8(float* c, const uint32_t* a, const uint32_t* b) {
    asm volatile(
        "mma.sync.aligned.m16n8k8.row.col.f32.tf32.tf32.f32 "
        "{%0,%1,%2,%3}, {%4,%5,%6,%7}, {%8,%9}, {%0,%1,%2,%3};"
        : "+f"(c[0]), "+f"(c[1]), "+f"(c[2]), "+f"(c[3])
        : "r"(a[0]), "r"(a[1]), "r"(a[2]), "r"(a[3]), "r"(b[0]), "r"(b[1]));
}

// ---------------- tf32 round pass ----------------
__global__ __launch_bounds__(256) void round_tf32_kernel(
    const float* __restrict__ in, float* __restrict__ out, int n4)
{
    int i = blockIdx.x * 256 + threadIdx.x;
    if (i < n4) {
        float4 v = ((const float4*)in)[i];
        v.x = __uint_as_float(tf32_rna(v.x));
        v.y = __uint_as_float(tf32_rna(v.y));
        v.z = __uint_as_float(tf32_rna(v.z));
        v.w = __uint_as_float(tf32_rna(v.w));
        ((float4*)out)[i] = v;
    }
}

// ---------------- pipelined tf32 GEMM core ----------------
// CTA tile 128x256, 8 warps (warp tile 64x64), K-chunk 32, 3-stage cp.async.
// Inputs A,B must already be tf32-valued fp32. B is [K][N] row-major.
#define A_PAD 36
#define B_PAD 264
#define A_STG (128*A_PAD)        // 4608 floats / stage
#define B_STG (32*B_PAD)         // 8448 floats / stage
#define GEMM_SMEM (3*(A_STG + B_STG)*4)   // 156672 B

template<bool RELU, bool ROUND>
__device__ __forceinline__ void gemm_body(
    const float* __restrict__ A, const float* __restrict__ Bm,
    const float* __restrict__ bias, float* __restrict__ C,
    int N, int K, int cn0, int tm, float* smf)
{
    const int tid  = threadIdx.x;
    const int lane = tid & 31;
    const int wid  = tid >> 5;
    const int wm   = wid & 1;
    const int wn   = wid >> 1;
    const int r4   = lane >> 2;
    const int t4   = lane & 3;

    // staging maps
    const int arow = tid >> 1, ac16 = (tid & 1) * 4;
    const int bkr  = tid >> 3, bc16 = (tid & 7) * 8;
    const uint32_t sbase = smem_u32(smf);
    const uint32_t aS = sbase + (uint32_t)(arow * A_PAD + ac16 * 4) * 4u;
    const uint32_t bS = sbase + (uint32_t)(3 * A_STG) * 4u + (uint32_t)(bkr * B_PAD + bc16 * 4) * 4u;
    const float* aG = A  + (size_t)(tm * 128 + arow) * K + ac16 * 4;
    const float* bG = Bm + (size_t)bkr * N + cn0 + bc16 * 4;

    auto issue = [&](int s, int c) {
        uint32_t a = aS + (uint32_t)s * (A_STG * 4);
        const float* ag = aG + c * 32;
        #pragma unroll
        for (int i = 0; i < 4; i++) cp16(a + i * 16, ag + i * 4);
        uint32_t b = bS + (uint32_t)s * (B_STG * 4);
        const float* bg = bG + (size_t)c * 32 * N;
        #pragma unroll
        for (int i = 0; i < 8; i++) cp16(b + i * 16, bg + i * 4);
    };

    float acc[4][8][4];
    #pragma unroll
    for (int i = 0; i < 4; i++)
        #pragma unroll
        for (int j = 0; j < 8; j++)
            #pragma unroll
            for (int t = 0; t < 4; t++) acc[i][j][t] = 0.f;

    const int NCH = K >> 5;
    issue(0, 0); asm volatile("cp.async.commit_group;");
    issue(1, 1); asm volatile("cp.async.commit_group;");

    for (int c = 0; c < NCH; c++) {
        asm volatile("cp.async.wait_group 1;");
        __syncthreads();
        if (c + 2 < NCH) issue((c + 2) % 3, c + 2);
        asm volatile("cp.async.commit_group;");

        const float* as = smf + (c % 3) * A_STG;
        const float* bs = smf + 3 * A_STG + (c % 3) * B_STG;
        #pragma unroll
        for (int ks = 0; ks < 4; ks++) {
            const int k0 = ks * 8;
            uint32_t af[4][4], bf[8][2];
            #pragma unroll
            for (int mi = 0; mi < 4; mi++) {
                const float* ar = as + (wm * 64 + mi * 16 + r4) * A_PAD + k0 + t4;
                af[mi][0] = __float_as_uint(ar[0]);
                af[mi][1] = __float_as_uint(ar[8 * A_PAD]);
                af[mi][2] = __float_as_uint(ar[4]);
                af[mi][3] = __float_as_uint(ar[8 * A_PAD + 4]);
            }
            #pragma unroll
            for (int ni = 0; ni < 8; ni++) {
                const float* br = bs + (k0 + t4) * B_PAD + wn * 64 + ni * 8 + r4;
                bf[ni][0] = __float_as_uint(br[0]);
                bf[ni][1] = __float_as_uint(br[4 * B_PAD]);
            }
            #pragma unroll
            for (int mi = 0; mi < 4; mi++)
                #pragma unroll
                for (int ni = 0; ni < 8; ni++)
                    mma16n8k8(acc[mi][ni], af[mi], bf[ni]);
        }
    }

    // epilogue
    #pragma unroll
    for (int mi = 0; mi < 4; mi++) {
        const int row0 = tm * 128 + wm * 64 + mi * 16 + r4;
        #pragma unroll
        for (int ni = 0; ni < 8; ni++) {
            const int col = cn0 + wn * 64 + ni * 8 + t4 * 2;
            const float b0 = bias[col], b1 = bias[col + 1];
            float2 v0, v1;
            v0.x = acc[mi][ni][0] + b0; v0.y = acc[mi][ni][1] + b1;
            v1.x = acc[mi][ni][2] + b0; v1.y = acc[mi][ni][3] + b1;
            if (RELU) {
                v0.x = fmaxf(v0.x, 0.f); v0.y = fmaxf(v0.y, 0.f);
                v1.x = fmaxf(v1.x, 0.f); v1.y = fmaxf(v1.y, 0.f);
            }
            if (ROUND) {
                v0.x = __uint_as_float(tf32_rna(v0.x));
                v0.y = __uint_as_float(tf32_rna(v0.y));
                v1.x = __uint_as_float(tf32_rna(v1.x));
                v1.y = __uint_as_float(tf32_rna(v1.y));
            }
            *(float2*)(C + (size_t)row0 * N + col)       = v0;
            *(float2*)(C + (size_t)(row0 + 8) * N + col) = v1;
        }
    }
}

template<bool RELU, bool ROUND>
__global__ __launch_bounds__(256, 1) void gemm_pipe(
    const float* __restrict__ A, const float* __restrict__ Bm,
    const float* __restrict__ bias, float* __restrict__ C, int N, int K)
{
    extern __shared__ float smf[];
    gemm_body<RELU, ROUND>(A, Bm, bias, C, N, K, blockIdx.x * 256, blockIdx.y, smf);
}

__global__ __launch_bounds__(256, 1) void gemm_qkv(
    const float* __restrict__ A,
    const float* __restrict__ Bq, const float* __restrict__ Bk, const float* __restrict__ Bv,
    const float* __restrict__ biq, const float* __restrict__ bik, const float* __restrict__ biv,
    float* __restrict__ Cq, float* __restrict__ Ck, float* __restrict__ Cv, int K)
{
    extern __shared__ float smf[];
    const int sel = blockIdx.x / 3;
    const int tn  = blockIdx.x % 3;
    const float* B  = (sel == 0) ? Bq  : (sel == 1) ? Bk  : Bv;
    const float* bi = (sel == 0) ? biq : (sel == 1) ? bik : biv;
    float*       C  = (sel == 0) ? Cq  : (sel == 1) ? Ck  : Cv;
    gemm_body<false, false>(A, B, bi, C, DD, K, tn * 256, blockIdx.y, smf);
}

// ---------------- Band attention: chunked online softmax, 64KB smem ----------------
#define ATTN_SMEM (2*128*64*4)

__global__ __launch_bounds__(128) void band_attn_kernel(
    const float* __restrict__ q, const float* __restrict__ k,
    const float* __restrict__ v, const float* __restrict__ xin,
    float* __restrict__ xout)
{
    extern __shared__ float smem[];
    float* ks = smem;               // 128*64
    float* vs = smem + 128*64;      // 128*64

    const int c  = blockIdx.x;
    const int h  = blockIdx.y;
    const int b  = blockIdx.z;
    const int qi = threadIdx.x;

    const int srow = c * WW + qi;
    const size_t qbase = ((size_t)(b * SS + srow)) * DD + h * DH;

    float qr[DH];
    #pragma unroll
    for (int d4 = 0; d4 < DH/4; d4++) {
        float4 t4 = *(const float4*)(q + qbase + d4*4);
        qr[d4*4+0] = t4.x * 0.125f;
        qr[d4*4+1] = t4.y * 0.125f;
        qr[d4*4+2] = t4.z * 0.125f;
        qr[d4*4+3] = t4.w * 0.125f;
    }

    float m = NEG_BIG, l = 0.f;
    float acc[DH];
    #pragma unroll
    for (int d = 0; d < DH; d++) acc[d] = 0.f;

    for (int t = 0; t < 3; t++) {
        // fully-masked boundary tiles (uniform per block)
        if ((t == 0 && c == 0) || (t == 2 && c == NC - 1)) continue;

        int ki_load = t * 128 + qi;
        int jg = c * WW + ki_load - WW;
        bool inr = (jg >= 0) && (jg < SS);
        size_t kb = ((size_t)(b * SS + (inr ? jg : 0))) * DD + h * DH;
        #pragma unroll
        for (int d4 = 0; d4 < DH/4; d4++) {
            float4 k4 = inr ? *(const float4*)(k + kb + d4*4) : make_float4(0,0,0,0);
            float4 v4 = inr ? *(const float4*)(v + kb + d4*4) : make_float4(0,0,0,0);
            *(float4*)(ks + qi*DH + d4*4) = k4;
            *(float4*)(vs + qi*DH + d4*4) = v4;
        }
        __syncthreads();

        #pragma unroll 1
        for (int jc = 0; jc < 8; jc++) {          // 8 chunks of 16 keys
            float sreg[16];
            float cmax = NEG_BIG;
            #pragma unroll
            for (int jj = 0; jj < 16; jj++) {
                int j = jc * 16 + jj;
                int ki = t * 128 + j;
                int jgj = c * WW + ki - WW;
                const float* kr = ks + j * DH;
                float s0 = 0.f, s1 = 0.f, s2 = 0.f, s3 = 0.f;
                #pragma unroll
                for (int d = 0; d < DH; d += 4) {
                    s0 += qr[d+0] * kr[d+0];
                    s1 += qr[d+1] * kr[d+1];
                    s2 += qr[d+2] * kr[d+2];
                    s3 += qr[d+3] * kr[d+3];
                }
                float s = (s0 + s1) + (s2 + s3);
                bool valid = (ki >= qi) && (ki <= qi + 2*WW) && (jgj >= 0) && (jgj < SS);
                s = valid ? s : NEG_BIG;
                sreg[jj] = s;
                cmax = fmaxf(cmax, s);
            }
            if (cmax > -1e29f) {
                float mnew = fmaxf(m, cmax);
                float scale = __expf(m - mnew);
                l *= scale;
                #pragma unroll
                for (int d = 0; d < DH; d++) acc[d] *= scale;
                #pragma unroll
                for (int jj = 0; jj < 16; jj++) {
                    float p = __expf(sreg[jj] - mnew);
                    l += p;
                    const float* vr = vs + (jc * 16 + jj) * DH;
                    #pragma unroll
                    for (int d = 0; d < DH; d++) acc[d] += p * vr[d];
                }
                m = mnew;
            }
        }
        __syncthreads();
    }

    float inv = 1.0f / l;
    #pragma unroll
    for (int d4 = 0; d4 < DH/4; d4++) {
        float4 xi = *(const float4*)(xin + qbase + d4*4);
        float4 o;
        o.x = xi.x + acc[d4*4+0] * inv;
        o.y = xi.y + acc[d4*4+1] * inv;
        o.z = xi.z + acc[d4*4+2] * inv;
        o.w = xi.w + acc[d4*4+3] * inv;
        *(float4*)(xout + qbase + d4*4) = o;
    }
}

// ---------------- fused add + LayerNorm ----------------
__device__ __forceinline__ float block_sum_256(float v, float* red) {
    int lane = threadIdx.x & 31;
    #pragma unroll
    for (int o = 16; o > 0; o >>= 1) v += __shfl_xor_sync(0xffffffffu, v, o);
    if (lane == 0) red[threadIdx.x >> 5] = v;
    __syncthreads();
    float r = (threadIdx.x < 8) ? red[threadIdx.x] : 0.f;
    if ((threadIdx.x >> 5) == 0) {
        #pragma unroll
        for (int o = 16; o > 0; o >>= 1) r += __shfl_xor_sync(0xffffffffu, r, o);
        if (lane == 0) red[0] = r;
    }
    __syncthreads();
    r = red[0];
    __syncthreads();
    return r;
}

__global__ __launch_bounds__(256) void add_ln_kernel(
    const float* __restrict__ x, const float* __restrict__ hh,
    const float* __restrict__ g, const float* __restrict__ bta,
    float* __restrict__ out, int hasH)
{
    __shared__ float red[8];
    const int row = blockIdx.x;
    const size_t base = (size_t)row * DD;
    const int t = threadIdx.x;

    float vals[3];
    float s = 0.f;
    #pragma unroll
    for (int i = 0; i < 3; i++) {
        int idx = t + i * 256;
        float vv = x[base + idx];
        if (hasH) vv += hh[base + idx];
        vals[i] = vv;
        s += vv;
    }
    float total = block_sum_256(s, red);
    float mu = total * (1.0f / DD);

    float vsum = 0.f;
    #pragma unroll
    for (int i = 0; i < 3; i++) {
        float d = vals[i] - mu;
        vsum += d * d;
    }
    float vtot = block_sum_256(vsum, red);
    float rstd = rsqrtf(vtot * (1.0f / DD) + 1e-6f);

    #pragma unroll
    for (int i = 0; i < 3; i++) {
        int idx = t + i * 256;
        out[base + idx] = (vals[i] - mu) * rstd * g[idx] + bta[idx];
    }
}

// ---------------- launcher ----------------
extern "C" void kernel_launch(void* const* d_in, const int* in_sizes, int n_in,
                              void* d_out, int out_size)
{
    const float* src   = (const float*)d_in[0];
    const float* Wq    = (const float*)d_in[1];
    const float* bq    = (const float*)d_in[2];
    const float* Wk    = (const float*)d_in[3];
    const float* bk    = (const float*)d_in[4];
    const float* Wv    = (const float*)d_in[5];
    const float* bv    = (const float*)d_in[6];
    const float* W1    = (const float*)d_in[7];
    const float* b1    = (const float*)d_in[8];
    const float* W2    = (const float*)d_in[9];
    const float* b2    = (const float*)d_in[10];
    const float* ln2_g = (const float*)d_in[11];
    const float* ln2_b = (const float*)d_in[12];
    const float* lnf_g = (const float*)d_in[13];
    const float* lnf_b = (const float*)d_in[14];

    float *x, *q, *k, *v, *h1, *h2, *xr, *wqr, *wkr, *wvr, *w1r, *w2r;
    cudaGetSymbolAddress((void**)&x,   g_x);
    cudaGetSymbolAddress((void**)&q,   g_q);
    cudaGetSymbolAddress((void**)&k,   g_k);
    cudaGetSymbolAddress((void**)&v,   g_v);
    cudaGetSymbolAddress((void**)&h1,  g_h1);
    cudaGetSymbolAddress((void**)&h2,  g_h2);
    cudaGetSymbolAddress((void**)&xr,  g_xr);
    cudaGetSymbolAddress((void**)&wqr, g_wqr);
    cudaGetSymbolAddress((void**)&wkr, g_wkr);
    cudaGetSymbolAddress((void**)&wvr, g_wvr);
    cudaGetSymbolAddress((void**)&w1r, g_w1r);
    cudaGetSymbolAddress((void**)&w2r, g_w2r);

    cudaFuncSetAttribute(band_attn_kernel,
                         cudaFuncAttributeMaxDynamicSharedMemorySize, ATTN_SMEM);
    cudaFuncSetAttribute(gemm_pipe<false,false>,
                         cudaFuncAttributeMaxDynamicSharedMemorySize, GEMM_SMEM);
    cudaFuncSetAttribute(gemm_pipe<true,true>,
                         cudaFuncAttributeMaxDynamicSharedMemorySize, GEMM_SMEM);
    cudaFuncSetAttribute(gemm_qkv,
                         cudaFuncAttributeMaxDynamicSharedMemorySize, GEMM_SMEM);

    // pre-round all weights to tf32 values (once per call)
    {
        int nqkv = LL * DD * DD / 4;
        int nff  = LL * DD * DFF / 4;
        round_tf32_kernel<<<(nqkv + 255) / 256, 256>>>(Wq, wqr, nqkv);
        round_tf32_kernel<<<(nqkv + 255) / 256, 256>>>(Wk, wkr, nqkv);
        round_tf32_kernel<<<(nqkv + 255) / 256, 256>>>(Wv, wvr, nqkv);
        round_tf32_kernel<<<(nff  + 255) / 256, 256>>>(W1, w1r, nff);
        round_tf32_kernel<<<(nff  + 255) / 256, 256>>>(W2, w2r, nff);
    }

    const int nx4 = MM * DD / 4;
    dim3 gQKV(9, MM / 128);          // fused q,k,v
    dim3 gF1(DFF / 256, MM / 128);   // (12, 64)
    dim3 gF2(DD / 256, MM / 128);    // (3, 64)
    dim3 gA(NC, HH, BB);

    for (int i = 0; i < LL; i++) {
        const float* xin = (i == 0) ? src : x;

        round_tf32_kernel<<<(nx4 + 255) / 256, 256>>>(xin, xr, nx4);
        gemm_qkv<<<gQKV, 256, GEMM_SMEM>>>(xr,
            wqr + (size_t)i*DD*DD, wkr + (size_t)i*DD*DD, wvr + (size_t)i*DD*DD,
            bq + i*DD, bk + i*DD, bv + i*DD, q, k, v, DD);

        band_attn_kernel<<<gA, 128, ATTN_SMEM>>>(q, k, v, xin, x);

        round_tf32_kernel<<<(nx4 + 255) / 256, 256>>>(x, xr, nx4);
        gemm_pipe<true,true><<<gF1, 256, GEMM_SMEM>>>(
            xr, w1r + (size_t)i*DD*DFF, b1 + i*DFF, h1, DFF, DD);
        gemm_pipe<false,false><<<gF2, 256, GEMM_SMEM>>>(
            h1, w2r + (size_t)i*DFF*DD, b2 + i*DD, h2, DD, DFF);

        add_ln_kernel<<<MM, 256>>>(x, h2, ln2_g + i*DD, ln2_b + i*DD, x, 1);
    }

    add_ln_kernel<<<MM, 256>>>(x, nullptr, lnf_g, lnf_b, (float*)d_out, 0);
}

// round 5
// speedup vs baseline: 2.9940x; 1.6686x over previous
#include <cuda_runtime.h>
#include <cuda_fp16.h>
#include <math.h>
#include <stdint.h>

// Problem constants
#define BB 2
#define SS 4096
#define DD 768
#define HH 12
#define LL 4
#define WW 128
#define DFF 3072
#define DH 64
#define MM (BB*SS)          // 8192 rows
#define NC (SS/WW)          // 32 chunks

#define NEG_BIG (-1e30f)

// ---------------- scratch buffers ----------------
__device__ float  g_x [MM*DD];
__device__ __half g_xh[MM*DD];           // fp16 copy of activation stream (GEMM A)
__device__ float  g_q [MM*DD];
__device__ float  g_k [MM*DD];
__device__ float  g_v [MM*DD];
__device__ __half g_h1[MM*DFF];          // FFN intermediate, fp16
__device__ float  g_h2[MM*DD];
// fp16 weights, transposed to [N][K]
__device__ __half g_wq[LL*DD*DD];
__device__ __half g_wk[LL*DD*DD];
__device__ __half g_wv[LL*DD*DD];
__device__ __half g_w1[LL*DD*DFF];
__device__ __half g_w2[LL*DFF*DD];

// ---------------- helpers ----------------
__device__ __forceinline__ uint32_t smem_u32(const void* p) {
    uint32_t a;
    asm("{ .reg .u64 t; cvta.to.shared.u64 t, %1; cvt.u32.u64 %0, t; }"
        : "=r"(a) : "l"(p));
    return a;
}
__device__ __forceinline__ void cp16(uint32_t s, const void* g) {
    asm volatile("cp.async.cg.shared.global [%0], [%1], 16;" :: "r"(s), "l"(g));
}
__device__ __forceinline__ void mma16n8k16(float* c, const uint32_t* a, const uint32_t* b) {
    asm volatile(
        "mma.sync.aligned.m16n8k16.row.col.f32.f16.f16.f32 "
        "{%0,%1,%2,%3}, {%4,%5,%6,%7}, {%8,%9}, {%0,%1,%2,%3};"
        : "+f"(c[0]), "+f"(c[1]), "+f"(c[2]), "+f"(c[3])
        : "r"(a[0]), "r"(a[1]), "r"(a[2]), "r"(a[3]), "r"(b[0]), "r"(b[1]));
}

// ---------------- conversion passes ----------------
__global__ __launch_bounds__(256) void f32_to_f16_kernel(
    const float* __restrict__ in, __half* __restrict__ out, int n4)
{
    int i = blockIdx.x * 256 + threadIdx.x;
    if (i < n4) {
        float4 v = ((const float4*)in)[i];
        ((__half2*)out)[i*2]   = __floats2half2_rn(v.x, v.y);
        ((__half2*)out)[i*2+1] = __floats2half2_rn(v.z, v.w);
    }
}

// transpose + convert: in f32 [R][C] -> out f16 [C][R]
__global__ __launch_bounds__(256) void trans_f16_kernel(
    const float* __restrict__ in, __half* __restrict__ out, int R, int C)
{
    __shared__ float t[32][33];
    const int bx = blockIdx.x * 32;   // C base
    const int by = blockIdx.y * 32;   // R base
    const int x = bx + threadIdx.x;
    #pragma unroll
    for (int i = threadIdx.y; i < 32; i += 8)
        t[i][threadIdx.x] = in[(size_t)(by + i) * C + x];
    __syncthreads();
    const int xo = by + threadIdx.x;
    #pragma unroll
    for (int i = threadIdx.y; i < 32; i += 8)
        out[(size_t)(bx + i) * R + xo] = __float2half(t[threadIdx.x][i]);
}

// ---------------- fp16 mma GEMM: C = A(MxK) @ Bt(NxK)^T + bias ----------------
// CTA tile 128x256, 8 warps (warp tile 64x64), K-chunk 32 halves, 3-stage cp.async.
// A [M][K] f16 row-major, Bt [N][K] f16 row-major (both K-major).
#define HPAD 40                     // halves per smem row (32 data + 8 pad)
#define A_STG (128*HPAD)            // halves per A stage
#define B_STG (256*HPAD)            // halves per B stage
#define GEMM_SMEM (3*(A_STG + B_STG)*2)   // 92160 B

template<bool RELU, bool OUTH>
__device__ __forceinline__ void gemm_body(
    const __half* __restrict__ A, const __half* __restrict__ Bt,
    const float* __restrict__ bias, float* __restrict__ Cf, __half* __restrict__ Ch,
    int N, int K, int cn0, int tm, __half* smh)
{
    const int tid  = threadIdx.x;
    const int lane = tid & 31;
    const int wid  = tid >> 5;
    const int wm   = wid & 1;
    const int wn   = wid >> 1;
    const int r4   = lane >> 2;
    const int t4   = lane & 3;

    // loader maps: 16B chunks (8 halves). A: 512 chunks/stage, B: 1024.
    const uint32_t sbase = smem_u32(smh);
    const int aid0 = tid, aid1 = tid + 256;
    const int arow0 = aid0 >> 2, akc0 = aid0 & 3;
    const int arow1 = aid1 >> 2, akc1 = aid1 & 3;
    const __half* aG0 = A + (size_t)(tm*128 + arow0) * K + akc0*8;
    const __half* aG1 = A + (size_t)(tm*128 + arow1) * K + akc1*8;
    const uint32_t aS0 = sbase + (uint32_t)(arow0*HPAD + akc0*8) * 2u;
    const uint32_t aS1 = sbase + (uint32_t)(arow1*HPAD + akc1*8) * 2u;

    const __half* bG[4];
    uint32_t bS[4];
    #pragma unroll
    for (int i = 0; i < 4; i++) {
        int id = tid + i*256;
        int row = id >> 2, kc = id & 3;
        bG[i] = Bt + (size_t)(cn0 + row) * K + kc*8;
        bS[i] = sbase + (uint32_t)(3*A_STG)*2u + (uint32_t)(row*HPAD + kc*8) * 2u;
    }

    auto issue = [&](int s, int c) {
        const uint32_t ao = (uint32_t)s * (A_STG*2);
        const uint32_t bo = (uint32_t)s * (B_STG*2);
        cp16(aS0 + ao, aG0 + c*32);
        cp16(aS1 + ao, aG1 + c*32);
        #pragma unroll
        for (int i = 0; i < 4; i++) cp16(bS[i] + bo, bG[i] + c*32);
    };

    float acc[4][8][4];
    #pragma unroll
    for (int i = 0; i < 4; i++)
        #pragma unroll
        for (int j = 0; j < 8; j++)
            #pragma unroll
            for (int t = 0; t < 4; t++) acc[i][j][t] = 0.f;

    const int NCH = K >> 5;
    issue(0, 0); asm volatile("cp.async.commit_group;");
    issue(1, 1); asm volatile("cp.async.commit_group;");

    for (int c = 0; c < NCH; c++) {
        asm volatile("cp.async.wait_group 1;");
        __syncthreads();
        if (c + 2 < NCH) issue((c + 2) % 3, c + 2);
        asm volatile("cp.async.commit_group;");

        const __half* as = smh + (c % 3) * A_STG;
        const __half* bs = smh + 3*A_STG + (c % 3) * B_STG;
        #pragma unroll
        for (int ks = 0; ks < 2; ks++) {          // 2 k16 steps per 32-chunk
            const int k0 = ks * 16;
            uint32_t af[4][4], bf[8][2];
            #pragma unroll
            for (int mi = 0; mi < 4; mi++) {
                const __half* ar = as + (wm*64 + mi*16 + r4) * HPAD + k0 + t4*2;
                af[mi][0] = *(const uint32_t*)(ar);
                af[mi][1] = *(const uint32_t*)(ar + 8*HPAD);
                af[mi][2] = *(const uint32_t*)(ar + 8);
                af[mi][3] = *(const uint32_t*)(ar + 8*HPAD + 8);
            }
            #pragma unroll
            for (int ni = 0; ni < 8; ni++) {
                const __half* br = bs + (wn*64 + ni*8 + r4) * HPAD + k0 + t4*2;
                bf[ni][0] = *(const uint32_t*)(br);
                bf[ni][1] = *(const uint32_t*)(br + 8);
            }
            #pragma unroll
            for (int mi = 0; mi < 4; mi++)
                #pragma unroll
                for (int ni = 0; ni < 8; ni++)
                    mma16n8k16(acc[mi][ni], af[mi], bf[ni]);
        }
    }

    // epilogue
    #pragma unroll
    for (int mi = 0; mi < 4; mi++) {
        const int row0 = tm*128 + wm*64 + mi*16 + r4;
        #pragma unroll
        for (int ni = 0; ni < 8; ni++) {
            const int col = cn0 + wn*64 + ni*8 + t4*2;
            const float b0 = bias[col], b1 = bias[col + 1];
            float2 v0, v1;
            v0.x = acc[mi][ni][0] + b0; v0.y = acc[mi][ni][1] + b1;
            v1.x = acc[mi][ni][2] + b0; v1.y = acc[mi][ni][3] + b1;
            if (RELU) {
                v0.x = fmaxf(v0.x, 0.f); v0.y = fmaxf(v0.y, 0.f);
                v1.x = fmaxf(v1.x, 0.f); v1.y = fmaxf(v1.y, 0.f);
            }
            if (OUTH) {
                *(__half2*)(Ch + (size_t)row0 * N + col)       = __floats2half2_rn(v0.x, v0.y);
                *(__half2*)(Ch + (size_t)(row0 + 8) * N + col) = __floats2half2_rn(v1.x, v1.y);
            } else {
                *(float2*)(Cf + (size_t)row0 * N + col)       = v0;
                *(float2*)(Cf + (size_t)(row0 + 8) * N + col) = v1;
            }
        }
    }
}

template<bool RELU, bool OUTH>
__global__ __launch_bounds__(256, 1) void gemm_f16(
    const __half* __restrict__ A, const __half* __restrict__ Bt,
    const float* __restrict__ bias, float* __restrict__ Cf, __half* __restrict__ Ch,
    int N, int K)
{
    extern __shared__ __half smh[];
    gemm_body<RELU, OUTH>(A, Bt, bias, Cf, Ch, N, K, blockIdx.x * 256, blockIdx.y, smh);
}

__global__ __launch_bounds__(256, 1) void gemm_qkv(
    const __half* __restrict__ A,
    const __half* __restrict__ Bq, const __half* __restrict__ Bk, const __half* __restrict__ Bv,
    const float* __restrict__ biq, const float* __restrict__ bik, const float* __restrict__ biv,
    float* __restrict__ Cq, float* __restrict__ Ck, float* __restrict__ Cv)
{
    extern __shared__ __half smh[];
    const int sel = blockIdx.x / 3;
    const int tn  = blockIdx.x % 3;
    const __half* B  = (sel == 0) ? Bq  : (sel == 1) ? Bk  : Bv;
    const float*  bi = (sel == 0) ? biq : (sel == 1) ? bik : biv;
    float*        C  = (sel == 0) ? Cq  : (sel == 1) ? Ck  : Cv;
    gemm_body<false, false>(A, B, bi, C, nullptr, DD, DD, tn * 256, blockIdx.y, smh);
}

// ---------------- Band attention: chunked online softmax ----------------
#define ATTN_SMEM (2*128*64*4)

__global__ __launch_bounds__(128) void band_attn_kernel(
    const float* __restrict__ q, const float* __restrict__ k,
    const float* __restrict__ v, const float* __restrict__ xin,
    float* __restrict__ xout, __half* __restrict__ xh)
{
    extern __shared__ float smem[];
    float* ks = smem;               // 128*64
    float* vs = smem + 128*64;      // 128*64

    const int c  = blockIdx.x;
    const int h  = blockIdx.y;
    const int b  = blockIdx.z;
    const int qi = threadIdx.x;

    const int srow = c * WW + qi;
    const size_t qbase = ((size_t)(b * SS + srow)) * DD + h * DH;

    float qr[DH];
    #pragma unroll
    for (int d4 = 0; d4 < DH/4; d4++) {
        float4 t4 = *(const float4*)(q + qbase + d4*4);
        qr[d4*4+0] = t4.x * 0.125f;
        qr[d4*4+1] = t4.y * 0.125f;
        qr[d4*4+2] = t4.z * 0.125f;
        qr[d4*4+3] = t4.w * 0.125f;
    }

    float m = NEG_BIG, l = 0.f;
    float acc[DH];
    #pragma unroll
    for (int d = 0; d < DH; d++) acc[d] = 0.f;

    for (int t = 0; t < 3; t++) {
        if ((t == 0 && c == 0) || (t == 2 && c == NC - 1)) continue;

        int ki_load = t * 128 + qi;
        int jg = c * WW + ki_load - WW;
        bool inr = (jg >= 0) && (jg < SS);
        size_t kb = ((size_t)(b * SS + (inr ? jg : 0))) * DD + h * DH;
        #pragma unroll
        for (int d4 = 0; d4 < DH/4; d4++) {
            float4 k4 = inr ? *(const float4*)(k + kb + d4*4) : make_float4(0,0,0,0);
            float4 v4 = inr ? *(const float4*)(v + kb + d4*4) : make_float4(0,0,0,0);
            *(float4*)(ks + qi*DH + d4*4) = k4;
            *(float4*)(vs + qi*DH + d4*4) = v4;
        }
        __syncthreads();

        #pragma unroll 1
        for (int jc = 0; jc < 8; jc++) {
            float sreg[16];
            float cmax = NEG_BIG;
            #pragma unroll
            for (int jj = 0; jj < 16; jj++) {
                int j = jc * 16 + jj;
                int ki = t * 128 + j;
                int jgj = c * WW + ki - WW;
                const float* kr = ks + j * DH;
                float s0 = 0.f, s1 = 0.f, s2 = 0.f, s3 = 0.f;
                #pragma unroll
                for (int d = 0; d < DH; d += 4) {
                    s0 += qr[d+0] * kr[d+0];
                    s1 += qr[d+1] * kr[d+1];
                    s2 += qr[d+2] * kr[d+2];
                    s3 += qr[d+3] * kr[d+3];
                }
                float s = (s0 + s1) + (s2 + s3);
                bool valid = (ki >= qi) && (ki <= qi + 2*WW) && (jgj >= 0) && (jgj < SS);
                s = valid ? s : NEG_BIG;
                sreg[jj] = s;
                cmax = fmaxf(cmax, s);
            }
            if (cmax > -1e29f) {
                float mnew = fmaxf(m, cmax);
                float scale = __expf(m - mnew);
                l *= scale;
                #pragma unroll
                for (int d = 0; d < DH; d++) acc[d] *= scale;
                #pragma unroll
                for (int jj = 0; jj < 16; jj++) {
                    float p = __expf(sreg[jj] - mnew);
                    l += p;
                    const float* vr = vs + (jc * 16 + jj) * DH;
                    #pragma unroll
                    for (int d = 0; d < DH; d++) acc[d] += p * vr[d];
                }
                m = mnew;
            }
        }
        __syncthreads();
    }

    float inv = 1.0f / l;
    #pragma unroll
    for (int d4 = 0; d4 < DH/4; d4++) {
        float4 xi = *(const float4*)(xin + qbase + d4*4);
        float4 o;
        o.x = xi.x + acc[d4*4+0] * inv;
        o.y = xi.y + acc[d4*4+1] * inv;
        o.z = xi.z + acc[d4*4+2] * inv;
        o.w = xi.w + acc[d4*4+3] * inv;
        *(float4*)(xout + qbase + d4*4) = o;
        *(__half2*)(xh + qbase + d4*4)     = __floats2half2_rn(o.x, o.y);
        *(__half2*)(xh + qbase + d4*4 + 2) = __floats2half2_rn(o.z, o.w);
    }
}

// ---------------- fused add + LayerNorm (dual fp32/fp16 output) ----------------
__device__ __forceinline__ float block_sum_256(float v, float* red) {
    int lane = threadIdx.x & 31;
    #pragma unroll
    for (int o = 16; o > 0; o >>= 1) v += __shfl_xor_sync(0xffffffffu, v, o);
    if (lane == 0) red[threadIdx.x >> 5] = v;
    __syncthreads();
    float r = (threadIdx.x < 8) ? red[threadIdx.x] : 0.f;
    if ((threadIdx.x >> 5) == 0) {
        #pragma unroll
        for (int o = 16; o > 0; o >>= 1) r += __shfl_xor_sync(0xffffffffu, r, o);
        if (lane == 0) red[0] = r;
    }
    __syncthreads();
    r = red[0];
    __syncthreads();
    return r;
}

__global__ __launch_bounds__(256) void add_ln_kernel(
    const float* __restrict__ x, const float* __restrict__ hh,
    const float* __restrict__ g, const float* __restrict__ bta,
    float* __restrict__ out, __half* __restrict__ outh, int hasH)
{
    __shared__ float red[8];
    const int row = blockIdx.x;
    const size_t base = (size_t)row * DD;
    const int t = threadIdx.x;

    float vals[3];
    float s = 0.f;
    #pragma unroll
    for (int i = 0; i < 3; i++) {
        int idx = t + i * 256;
        float vv = x[base + idx];
        if (hasH) vv += hh[base + idx];
        vals[i] = vv;
        s += vv;
    }
    float total = block_sum_256(s, red);
    float mu = total * (1.0f / DD);

    float vsum = 0.f;
    #pragma unroll
    for (int i = 0; i < 3; i++) {
        float d = vals[i] - mu;
        vsum += d * d;
    }
    float vtot = block_sum_256(vsum, red);
    float rstd = rsqrtf(vtot * (1.0f / DD) + 1e-6f);

    #pragma unroll
    for (int i = 0; i < 3; i++) {
        int idx = t + i * 256;
        float o = (vals[i] - mu) * rstd * g[idx] + bta[idx];
        out[base + idx] = o;
        if (outh) outh[base + idx] = __float2half(o);
    }
}

// ---------------- launcher ----------------
extern "C" void kernel_launch(void* const* d_in, const int* in_sizes, int n_in,
                              void* d_out, int out_size)
{
    const float* src   = (const float*)d_in[0];
    const float* Wq    = (const float*)d_in[1];
    const float* bq    = (const float*)d_in[2];
    const float* Wk    = (const float*)d_in[3];
    const float* bk    = (const float*)d_in[4];
    const float* Wv    = (const float*)d_in[5];
    const float* bv    = (const float*)d_in[6];
    const float* W1    = (const float*)d_in[7];
    const float* b1    = (const float*)d_in[8];
    const float* W2    = (const float*)d_in[9];
    const float* b2    = (const float*)d_in[10];
    const float* ln2_g = (const float*)d_in[11];
    const float* ln2_b = (const float*)d_in[12];
    const float* lnf_g = (const float*)d_in[13];
    const float* lnf_b = (const float*)d_in[14];

    float *x, *q, *k, *v, *h2;
    __half *xh, *h1, *wq, *wk, *wv, *w1, *w2;
    cudaGetSymbolAddress((void**)&x,  g_x);
    cudaGetSymbolAddress((void**)&xh, g_xh);
    cudaGetSymbolAddress((void**)&q,  g_q);
    cudaGetSymbolAddress((void**)&k,  g_k);
    cudaGetSymbolAddress((void**)&v,  g_v);
    cudaGetSymbolAddress((void**)&h1, g_h1);
    cudaGetSymbolAddress((void**)&h2, g_h2);
    cudaGetSymbolAddress((void**)&wq, g_wq);
    cudaGetSymbolAddress((void**)&wk, g_wk);
    cudaGetSymbolAddress((void**)&wv, g_wv);
    cudaGetSymbolAddress((void**)&w1, g_w1);
    cudaGetSymbolAddress((void**)&w2, g_w2);

    cudaFuncSetAttribute(band_attn_kernel,
                         cudaFuncAttributeMaxDynamicSharedMemorySize, ATTN_SMEM);
    cudaFuncSetAttribute(gemm_f16<true,true>,
                         cudaFuncAttributeMaxDynamicSharedMemorySize, GEMM_SMEM);
    cudaFuncSetAttribute(gemm_f16<false,false>,
                         cudaFuncAttributeMaxDynamicSharedMemorySize, GEMM_SMEM);
    cudaFuncSetAttribute(gemm_qkv,
                         cudaFuncAttributeMaxDynamicSharedMemorySize, GEMM_SMEM);

    // weight transpose+convert to fp16 [N][K], once per call
    {
        dim3 blk(32, 8);
        dim3 gDD(DD/32, DD/32);      // [768][768] -> [768][768]
        dim3 gW1(DFF/32, DD/32);     // [768][3072] -> [3072][768]
        dim3 gW2(DD/32, DFF/32);     // [3072][768] -> [768][3072]
        for (int i = 0; i < LL; i++) {
            trans_f16_kernel<<<gDD, blk>>>(Wq + (size_t)i*DD*DD,  wq + (size_t)i*DD*DD,  DD, DD);
            trans_f16_kernel<<<gDD, blk>>>(Wk + (size_t)i*DD*DD,  wk + (size_t)i*DD*DD,  DD, DD);
            trans_f16_kernel<<<gDD, blk>>>(Wv + (size_t)i*DD*DD,  wv + (size_t)i*DD*DD,  DD, DD);
            trans_f16_kernel<<<gW1, blk>>>(W1 + (size_t)i*DD*DFF, w1 + (size_t)i*DD*DFF, DD, DFF);
            trans_f16_kernel<<<gW2, blk>>>(W2 + (size_t)i*DFF*DD, w2 + (size_t)i*DFF*DD, DFF, DD);
        }
    }

    // src -> fp16 for layer-0 QKV
    f32_to_f16_kernel<<<(MM*DD/4 + 255)/256, 256>>>(src, xh, MM*DD/4);

    dim3 gQKV(9, MM/128);
    dim3 gF1(DFF/256, MM/128);   // (12, 64)
    dim3 gF2(DD/256, MM/128);    // (3, 64)
    dim3 gA(NC, HH, BB);

    for (int i = 0; i < LL; i++) {
        const float* xin = (i == 0) ? src : x;

        gemm_qkv<<<gQKV, 256, GEMM_SMEM>>>(xh,
            wq + (size_t)i*DD*DD, wk + (size_t)i*DD*DD, wv + (size_t)i*DD*DD,
            bq + i*DD, bk + i*DD, bv + i*DD, q, k, v);

        band_attn_kernel<<<gA, 128, ATTN_SMEM>>>(q, k, v, xin, x, xh);

        gemm_f16<true,true><<<gF1, 256, GEMM_SMEM>>>(
            xh, w1 + (size_t)i*DD*DFF, b1 + i*DFF, nullptr, h1, DFF, DD);
        gemm_f16<false,false><<<gF2, 256, GEMM_SMEM>>>(
            h1, w2 + (size_t)i*DFF*DD, b2 + i*DD, h2, nullptr, DD, DFF);

        add_ln_kernel<<<MM, 256>>>(x, h2, ln2_g + i*DD, ln2_b + i*DD, x, xh, 1);
    }

    add_ln_kernel<<<MM, 256>>>(x, nullptr, lnf_g, lnf_b, (float*)d_out, nullptr, 0);
}

// round 6
// speedup vs baseline: 4.9437x; 1.6512x over previous
#include <cuda_runtime.h>
#include <cuda_fp16.h>
#include <math.h>
#include <stdint.h>

// Problem constants
#define BB 2
#define SS 4096
#define DD 768
#define HH 12
#define LL 4
#define WW 128
#define DFF 3072
#define DH 64
#define MM (BB*SS)          // 8192 rows
#define NC (SS/WW)          // 32 chunks

#define NEG_BIG (-1e30f)

// ---------------- scratch buffers ----------------
__device__ float  g_x [MM*DD];
__device__ __half g_xh[MM*DD];           // fp16 activation stream (GEMM A)
__device__ __half g_qh[MM*DD];           // fp16 q (pre-scaled by 1/8), k, v
__device__ __half g_kh[MM*DD];
__device__ __half g_vh[MM*DD];
__device__ __half g_h1[MM*DFF];          // FFN intermediate, fp16
__device__ float  g_h2[MM*DD];
// fp16 weights, transposed to [N][K]
__device__ __half g_wq[LL*DD*DD];
__device__ __half g_wk[LL*DD*DD];
__device__ __half g_wv[LL*DD*DD];
__device__ __half g_w1[LL*DD*DFF];
__device__ __half g_w2[LL*DFF*DD];

// ---------------- helpers ----------------
__device__ __forceinline__ uint32_t smem_u32(const void* p) {
    uint32_t a;
    asm("{ .reg .u64 t; cvta.to.shared.u64 t, %1; cvt.u32.u64 %0, t; }"
        : "=r"(a) : "l"(p));
    return a;
}
__device__ __forceinline__ void cp16(uint32_t s, const void* g) {
    asm volatile("cp.async.cg.shared.global [%0], [%1], 16;" :: "r"(s), "l"(g));
}
__device__ __forceinline__ void mma16n8k16(float* c, const uint32_t* a, const uint32_t* b) {
    asm volatile(
        "mma.sync.aligned.m16n8k16.row.col.f32.f16.f16.f32 "
        "{%0,%1,%2,%3}, {%4,%5,%6,%7}, {%8,%9}, {%0,%1,%2,%3};"
        : "+f"(c[0]), "+f"(c[1]), "+f"(c[2]), "+f"(c[3])
        : "r"(a[0]), "r"(a[1]), "r"(a[2]), "r"(a[3]), "r"(b[0]), "r"(b[1]));
}
__device__ __forceinline__ uint32_t h2pack(float a, float b) {
    __half2 h = __floats2half2_rn(a, b);
    return *(uint32_t*)&h;
}

// ---------------- conversion passes ----------------
__global__ __launch_bounds__(256) void f32_to_f16_kernel(
    const float* __restrict__ in, __half* __restrict__ out, int n4)
{
    int i = blockIdx.x * 256 + threadIdx.x;
    if (i < n4) {
        float4 v = ((const float4*)in)[i];
        ((__half2*)out)[i*2]   = __floats2half2_rn(v.x, v.y);
        ((__half2*)out)[i*2+1] = __floats2half2_rn(v.z, v.w);
    }
}

// transpose + convert: in f32 [R][C] -> out f16 [C][R], batched over layers (z)
__global__ __launch_bounds__(256) void trans_f16_kernel(
    const float* __restrict__ in, __half* __restrict__ out, int R, int C)
{
    __shared__ float t[32][33];
    const size_t lo = (size_t)blockIdx.z * R * C;
    const int bx = blockIdx.x * 32;
    const int by = blockIdx.y * 32;
    const int x = bx + threadIdx.x;
    #pragma unroll
    for (int i = threadIdx.y; i < 32; i += 8)
        t[i][threadIdx.x] = in[lo + (size_t)(by + i) * C + x];
    __syncthreads();
    const int xo = by + threadIdx.x;
    #pragma unroll
    for (int i = threadIdx.y; i < 32; i += 8)
        out[lo + (size_t)(bx + i) * R + xo] = __float2half(t[threadIdx.x][i]);
}

// ---------------- fp16 mma GEMM: C = A(MxK) @ Bt(NxK)^T + bias ----------------
#define HPAD 40
#define A_STG (128*HPAD)
#define B_STG (256*HPAD)
#define GEMM_SMEM (3*(A_STG + B_STG)*2)   // 92160 B

template<bool RELU, bool OUTH>
__device__ __forceinline__ void gemm_body(
    const __half* __restrict__ A, const __half* __restrict__ Bt,
    const float* __restrict__ bias, float* __restrict__ Cf, __half* __restrict__ Ch,
    int N, int K, int cn0, int tm, __half* smh, float oscale)
{
    const int tid  = threadIdx.x;
    const int lane = tid & 31;
    const int wid  = tid >> 5;
    const int wm   = wid & 1;
    const int wn   = wid >> 1;
    const int r4   = lane >> 2;
    const int t4   = lane & 3;

    const uint32_t sbase = smem_u32(smh);
    const int aid0 = tid, aid1 = tid + 256;
    const int arow0 = aid0 >> 2, akc0 = aid0 & 3;
    const int arow1 = aid1 >> 2, akc1 = aid1 & 3;
    const __half* aG0 = A + (size_t)(tm*128 + arow0) * K + akc0*8;
    const __half* aG1 = A + (size_t)(tm*128 + arow1) * K + akc1*8;
    const uint32_t aS0 = sbase + (uint32_t)(arow0*HPAD + akc0*8) * 2u;
    const uint32_t aS1 = sbase + (uint32_t)(arow1*HPAD + akc1*8) * 2u;

    const __half* bG[4];
    uint32_t bS[4];
    #pragma unroll
    for (int i = 0; i < 4; i++) {
        int id = tid + i*256;
        int row = id >> 2, kc = id & 3;
        bG[i] = Bt + (size_t)(cn0 + row) * K + kc*8;
        bS[i] = sbase + (uint32_t)(3*A_STG)*2u + (uint32_t)(row*HPAD + kc*8) * 2u;
    }

    auto issue = [&](int s, int c) {
        const uint32_t ao = (uint32_t)s * (A_STG*2);
        const uint32_t bo = (uint32_t)s * (B_STG*2);
        cp16(aS0 + ao, aG0 + c*32);
        cp16(aS1 + ao, aG1 + c*32);
        #pragma unroll
        for (int i = 0; i < 4; i++) cp16(bS[i] + bo, bG[i] + c*32);
    };

    float acc[4][8][4];
    #pragma unroll
    for (int i = 0; i < 4; i++)
        #pragma unroll
        for (int j = 0; j < 8; j++)
            #pragma unroll
            for (int t = 0; t < 4; t++) acc[i][j][t] = 0.f;

    const int NCH = K >> 5;
    issue(0, 0); asm volatile("cp.async.commit_group;");
    issue(1, 1); asm volatile("cp.async.commit_group;");

    for (int c = 0; c < NCH; c++) {
        asm volatile("cp.async.wait_group 1;");
        __syncthreads();
        if (c + 2 < NCH) issue((c + 2) % 3, c + 2);
        asm volatile("cp.async.commit_group;");

        const __half* as = smh + (c % 3) * A_STG;
        const __half* bs = smh + 3*A_STG + (c % 3) * B_STG;
        #pragma unroll
        for (int ks = 0; ks < 2; ks++) {
            const int k0 = ks * 16;
            uint32_t af[4][4], bf[8][2];
            #pragma unroll
            for (int mi = 0; mi < 4; mi++) {
                const __half* ar = as + (wm*64 + mi*16 + r4) * HPAD + k0 + t4*2;
                af[mi][0] = *(const uint32_t*)(ar);
                af[mi][1] = *(const uint32_t*)(ar + 8*HPAD);
                af[mi][2] = *(const uint32_t*)(ar + 8);
                af[mi][3] = *(const uint32_t*)(ar + 8*HPAD + 8);
            }
            #pragma unroll
            for (int ni = 0; ni < 8; ni++) {
                const __half* br = bs + (wn*64 + ni*8 + r4) * HPAD + k0 + t4*2;
                bf[ni][0] = *(const uint32_t*)(br);
                bf[ni][1] = *(const uint32_t*)(br + 8);
            }
            #pragma unroll
            for (int mi = 0; mi < 4; mi++)
                #pragma unroll
                for (int ni = 0; ni < 8; ni++)
                    mma16n8k16(acc[mi][ni], af[mi], bf[ni]);
        }
    }

    #pragma unroll
    for (int mi = 0; mi < 4; mi++) {
        const int row0 = tm*128 + wm*64 + mi*16 + r4;
        #pragma unroll
        for (int ni = 0; ni < 8; ni++) {
            const int col = cn0 + wn*64 + ni*8 + t4*2;
            const float b0 = bias[col], b1 = bias[col + 1];
            float2 v0, v1;
            v0.x = acc[mi][ni][0] + b0; v0.y = acc[mi][ni][1] + b1;
            v1.x = acc[mi][ni][2] + b0; v1.y = acc[mi][ni][3] + b1;
            if (RELU) {
                v0.x = fmaxf(v0.x, 0.f); v0.y = fmaxf(v0.y, 0.f);
                v1.x = fmaxf(v1.x, 0.f); v1.y = fmaxf(v1.y, 0.f);
            }
            if (OUTH) {
                v0.x *= oscale; v0.y *= oscale; v1.x *= oscale; v1.y *= oscale;
                *(__half2*)(Ch + (size_t)row0 * N + col)       = __floats2half2_rn(v0.x, v0.y);
                *(__half2*)(Ch + (size_t)(row0 + 8) * N + col) = __floats2half2_rn(v1.x, v1.y);
            } else {
                *(float2*)(Cf + (size_t)row0 * N + col)       = v0;
                *(float2*)(Cf + (size_t)(row0 + 8) * N + col) = v1;
            }
        }
    }
}

template<bool RELU, bool OUTH>
__global__ __launch_bounds__(256, 1) void gemm_f16(
    const __half* __restrict__ A, const __half* __restrict__ Bt,
    const float* __restrict__ bias, float* __restrict__ Cf, __half* __restrict__ Ch,
    int N, int K)
{
    extern __shared__ __half smh[];
    gemm_body<RELU, OUTH>(A, Bt, bias, Cf, Ch, N, K, blockIdx.x * 256, blockIdx.y, smh, 1.0f);
}

__global__ __launch_bounds__(256, 1) void gemm_qkv(
    const __half* __restrict__ A,
    const __half* __restrict__ Bq, const __half* __restrict__ Bk, const __half* __restrict__ Bv,
    const float* __restrict__ biq, const float* __restrict__ bik, const float* __restrict__ biv,
    __half* __restrict__ Cq, __half* __restrict__ Ck, __half* __restrict__ Cv)
{
    extern __shared__ __half smh[];
    const int sel = blockIdx.x / 3;
    const int tn  = blockIdx.x % 3;
    const __half* B  = (sel == 0) ? Bq  : (sel == 1) ? Bk  : Bv;
    const float*  bi = (sel == 0) ? biq : (sel == 1) ? bik : biv;
    __half*       C  = (sel == 0) ? Cq  : (sel == 1) ? Ck  : Cv;
    const float   sc = (sel == 0) ? 0.125f : 1.0f;
    gemm_body<false, true>(A, B, bi, nullptr, C, DD, DD, tn * 256, blockIdx.y, smh, sc);
}

// ---------------- tensor-core band attention ----------------
// CTA = (chunk c, head h, batch b). 8 warps x 16 query rows = 128 queries.
// Per key tile (128): S = Q@K^T (m16n8k16), online softmax in frag layout, P@V.
#define QP 72                       // halves per qs/ks row (64 + 8)
#define VP 136                      // halves per vt row (128 + 8)
#define ATTN_SMEM ((2*128*QP + 64*VP)*2)   // 54272 B

__global__ __launch_bounds__(256) void band_attn_tc(
    const __half* __restrict__ q, const __half* __restrict__ k,
    const __half* __restrict__ v, const float* __restrict__ xin,
    float* __restrict__ xout, __half* __restrict__ xh)
{
    extern __shared__ __half sm[];
    __half* qs = sm;                  // 128 x QP
    __half* ks = sm + 128*QP;         // 128 x QP
    __half* vt = sm + 2*128*QP;       // 64 x VP (transposed V)

    const int c = blockIdx.x, h = blockIdx.y, b = blockIdx.z;
    const int tid  = threadIdx.x;
    const int lane = tid & 31;
    const int w    = tid >> 5;
    const int r4   = lane >> 2, t4 = lane & 3;
    const int wrow = w * 16;

    const uint32_t qsu = smem_u32(qs);
    const uint32_t ksu = smem_u32(ks);

    // Q tile: 128 rows x 64 halves, cp.async
    {
        const int row = tid >> 1, ch = (tid & 1) * 4;
        const __half* gq = q + (size_t)(b*SS + c*WW + row) * DD + h*DH + ch*8;
        const uint32_t ds = qsu + (uint32_t)(row*QP + ch*8) * 2u;
        #pragma unroll
        for (int i = 0; i < 4; i++) cp16(ds + i*16, gq + i*8);
    }
    asm volatile("cp.async.commit_group;");

    float Of[8][4];
    #pragma unroll
    for (int i = 0; i < 8; i++)
        #pragma unroll
        for (int j = 0; j < 4; j++) Of[i][j] = 0.f;
    float m0 = NEG_BIG, m1 = NEG_BIG, l0 = 0.f, l1 = 0.f;
    uint32_t qa[4][4];

    const int tbeg = (c == 0) ? 1 : 0;
    const int tend = (c == NC-1) ? 1 : 2;

    for (int t = tbeg; t <= tend; t++) {
        __syncthreads();    // protect ks/vt reuse across tiles
        // K tile
        {
            const int row = tid >> 1, ch = (tid & 1) * 4;
            const int jg = c*WW + t*128 - WW + row;
            const __half* gk = k + (size_t)(b*SS + jg) * DD + h*DH + ch*8;
            const uint32_t ds = ksu + (uint32_t)(row*QP + ch*8) * 2u;
            #pragma unroll
            for (int i = 0; i < 4; i++) cp16(ds + i*16, gk + i*8);
        }
        asm volatile("cp.async.commit_group;");
        // V tile -> transposed into vt[dim][key]
        {
            const int key = tid >> 1, d0 = (tid & 1) * 32;
            const int jg = c*WW + t*128 - WW + key;
            const __half* gv = v + (size_t)(b*SS + jg) * DD + h*DH + d0;
            #pragma unroll
            for (int i = 0; i < 4; i++) {
                uint4 u = *(const uint4*)(gv + i*8);
                const __half* hp = (const __half*)&u;
                #pragma unroll
                for (int d = 0; d < 8; d++)
                    vt[(d0 + i*8 + d)*VP + key] = hp[d];
            }
        }
        asm volatile("cp.async.wait_group 0;");
        __syncthreads();

        if (t == tbeg) {   // Q fragments, loaded once
            #pragma unroll
            for (int kk = 0; kk < 4; kk++) {
                const __half* ar = qs + (wrow + r4)*QP + kk*16 + t4*2;
                qa[kk][0] = *(const uint32_t*)(ar);
                qa[kk][1] = *(const uint32_t*)(ar + 8*QP);
                qa[kk][2] = *(const uint32_t*)(ar + 8);
                qa[kk][3] = *(const uint32_t*)(ar + 8*QP + 8);
            }
        }

        // S = Q @ K^T : 16 n-frags x 4 k-steps
        float S[16][4];
        #pragma unroll
        for (int j = 0; j < 16; j++) {
            S[j][0] = S[j][1] = S[j][2] = S[j][3] = 0.f;
            #pragma unroll
            for (int kk = 0; kk < 4; kk++) {
                uint32_t bf[2];
                const __half* br = ks + (j*8 + r4)*QP + kk*16 + t4*2;
                bf[0] = *(const uint32_t*)(br);
                bf[1] = *(const uint32_t*)(br + 8);
                mma16n8k16(S[j], qa[kk], bf);
            }
        }

        // band mask: tile1 unmasked; tile0: key >= qi; tile2: key <= qi
        if (t == 0) {
            #pragma unroll
            for (int j = 0; j < 16; j++) {
                const int key0 = j*8 + t4*2;
                const int q0 = wrow + r4, q1 = q0 + 8;
                if (key0     < q0) S[j][0] = NEG_BIG;
                if (key0 + 1 < q0) S[j][1] = NEG_BIG;
                if (key0     < q1) S[j][2] = NEG_BIG;
                if (key0 + 1 < q1) S[j][3] = NEG_BIG;
            }
        } else if (t == 2) {
            #pragma unroll
            for (int j = 0; j < 16; j++) {
                const int key0 = j*8 + t4*2;
                const int q0 = wrow + r4, q1 = q0 + 8;
                if (key0     > q0) S[j][0] = NEG_BIG;
                if (key0 + 1 > q0) S[j][1] = NEG_BIG;
                if (key0     > q1) S[j][2] = NEG_BIG;
                if (key0 + 1 > q1) S[j][3] = NEG_BIG;
            }
        }

        // row max (rows r4 / r4+8), quad reduce
        float mx0 = NEG_BIG, mx1 = NEG_BIG;
        #pragma unroll
        for (int j = 0; j < 16; j++) {
            mx0 = fmaxf(mx0, fmaxf(S[j][0], S[j][1]));
            mx1 = fmaxf(mx1, fmaxf(S[j][2], S[j][3]));
        }
        mx0 = fmaxf(mx0, __shfl_xor_sync(0xffffffffu, mx0, 1));
        mx0 = fmaxf(mx0, __shfl_xor_sync(0xffffffffu, mx0, 2));
        mx1 = fmaxf(mx1, __shfl_xor_sync(0xffffffffu, mx1, 1));
        mx1 = fmaxf(mx1, __shfl_xor_sync(0xffffffffu, mx1, 2));

        const float mn0 = fmaxf(m0, mx0), mn1 = fmaxf(m1, mx1);
        const float sc0 = __expf(m0 - mn0), sc1 = __expf(m1 - mn1);
        m0 = mn0; m1 = mn1;
        l0 *= sc0; l1 *= sc1;
        #pragma unroll
        for (int nf = 0; nf < 8; nf++) {
            Of[nf][0] *= sc0; Of[nf][1] *= sc0;
            Of[nf][2] *= sc1; Of[nf][3] *= sc1;
        }

        // exp -> P frags (per 16-key step), then P @ V
        #pragma unroll
        for (int kk = 0; kk < 8; kk++) {
            const float p00 = __expf(S[2*kk][0]   - m0);
            const float p01 = __expf(S[2*kk][1]   - m0);
            const float p02 = __expf(S[2*kk][2]   - m1);
            const float p03 = __expf(S[2*kk][3]   - m1);
            const float p10 = __expf(S[2*kk+1][0] - m0);
            const float p11 = __expf(S[2*kk+1][1] - m0);
            const float p12 = __expf(S[2*kk+1][2] - m1);
            const float p13 = __expf(S[2*kk+1][3] - m1);
            l0 += p00 + p01 + p10 + p11;
            l1 += p02 + p03 + p12 + p13;
            uint32_t pa[4];
            pa[0] = h2pack(p00, p01);
            pa[1] = h2pack(p02, p03);
            pa[2] = h2pack(p10, p11);
            pa[3] = h2pack(p12, p13);
            #pragma unroll
            for (int nf = 0; nf < 8; nf++) {
                uint32_t bf[2];
                const __half* br = vt + (nf*8 + r4)*VP + kk*16 + t4*2;
                bf[0] = *(const uint32_t*)(br);
                bf[1] = *(const uint32_t*)(br + 8);
                mma16n8k16(Of[nf], pa, bf);
            }
        }
    }

    // finalize: full row sums via quad reduce, then residual write
    l0 += __shfl_xor_sync(0xffffffffu, l0, 1);
    l0 += __shfl_xor_sync(0xffffffffu, l0, 2);
    l1 += __shfl_xor_sync(0xffffffffu, l1, 1);
    l1 += __shfl_xor_sync(0xffffffffu, l1, 2);
    const float inv0 = 1.0f / l0, inv1 = 1.0f / l1;

    const size_t rb0 = (size_t)(b*SS + c*WW + wrow + r4) * DD + h*DH;
    const size_t rb1 = rb0 + 8*DD;
    #pragma unroll
    for (int nf = 0; nf < 8; nf++) {
        const int col = nf*8 + t4*2;
        float2 o0, o1;
        o0.x = xin[rb0 + col]     + Of[nf][0] * inv0;
        o0.y = xin[rb0 + col + 1] + Of[nf][1] * inv0;
        o1.x = xin[rb1 + col]     + Of[nf][2] * inv1;
        o1.y = xin[rb1 + col + 1] + Of[nf][3] * inv1;
        *(float2*)(xout + rb0 + col) = o0;
        *(float2*)(xout + rb1 + col) = o1;
        *(__half2*)(xh + rb0 + col) = __floats2half2_rn(o0.x, o0.y);
        *(__half2*)(xh + rb1 + col) = __floats2half2_rn(o1.x, o1.y);
    }
}

// ---------------- fused add + LayerNorm (dual fp32/fp16 output) ----------------
__device__ __forceinline__ float block_sum_256(float v, float* red) {
    int lane = threadIdx.x & 31;
    #pragma unroll
    for (int o = 16; o > 0; o >>= 1) v += __shfl_xor_sync(0xffffffffu, v, o);
    if (lane == 0) red[threadIdx.x >> 5] = v;
    __syncthreads();
    float r = (threadIdx.x < 8) ? red[threadIdx.x] : 0.f;
    if ((threadIdx.x >> 5) == 0) {
        #pragma unroll
        for (int o = 16; o > 0; o >>= 1) r += __shfl_xor_sync(0xffffffffu, r, o);
        if (lane == 0) red[0] = r;
    }
    __syncthreads();
    r = red[0];
    __syncthreads();
    return r;
}

__global__ __launch_bounds__(256) void add_ln_kernel(
    const float* __restrict__ x, const float* __restrict__ hh,
    const float* __restrict__ g, const float* __restrict__ bta,
    float* __restrict__ out, __half* __restrict__ outh, int hasH)
{
    __shared__ float red[8];
    const int row = blockIdx.x;
    const size_t base = (size_t)row * DD;
    const int t = threadIdx.x;

    float vals[3];
    float s = 0.f;
    #pragma unroll
    for (int i = 0; i < 3; i++) {
        int idx = t + i * 256;
        float vv = x[base + idx];
        if (hasH) vv += hh[base + idx];
        vals[i] = vv;
        s += vv;
    }
    float total = block_sum_256(s, red);
    float mu = total * (1.0f / DD);

    float vsum = 0.f;
    #pragma unroll
    for (int i = 0; i < 3; i++) {
        float d = vals[i] - mu;
        vsum += d * d;
    }
    float vtot = block_sum_256(vsum, red);
    float rstd = rsqrtf(vtot * (1.0f / DD) + 1e-6f);

    #pragma unroll
    for (int i = 0; i < 3; i++) {
        int idx = t + i * 256;
        float o = (vals[i] - mu) * rstd * g[idx] + bta[idx];
        out[base + idx] = o;
        if (outh) outh[base + idx] = __float2half(o);
    }
}

// ---------------- launcher ----------------
extern "C" void kernel_launch(void* const* d_in, const int* in_sizes, int n_in,
                              void* d_out, int out_size)
{
    const float* src   = (const float*)d_in[0];
    const float* Wq    = (const float*)d_in[1];
    const float* bq    = (const float*)d_in[2];
    const float* Wk    = (const float*)d_in[3];
    const float* bk    = (const float*)d_in[4];
    const float* Wv    = (const float*)d_in[5];
    const float* bv    = (const float*)d_in[6];
    const float* W1    = (const float*)d_in[7];
    const float* b1    = (const float*)d_in[8];
    const float* W2    = (const float*)d_in[9];
    const float* b2    = (const float*)d_in[10];
    const float* ln2_g = (const float*)d_in[11];
    const float* ln2_b = (const float*)d_in[12];
    const float* lnf_g = (const float*)d_in[13];
    const float* lnf_b = (const float*)d_in[14];

    float *x, *h2;
    __half *xh, *qh, *kh, *vh, *h1, *wq, *wk, *wv, *w1, *w2;
    cudaGetSymbolAddress((void**)&x,  g_x);
    cudaGetSymbolAddress((void**)&xh, g_xh);
    cudaGetSymbolAddress((void**)&qh, g_qh);
    cudaGetSymbolAddress((void**)&kh, g_kh);
    cudaGetSymbolAddress((void**)&vh, g_vh);
    cudaGetSymbolAddress((void**)&h1, g_h1);
    cudaGetSymbolAddress((void**)&h2, g_h2);
    cudaGetSymbolAddress((void**)&wq, g_wq);
    cudaGetSymbolAddress((void**)&wk, g_wk);
    cudaGetSymbolAddress((void**)&wv, g_wv);
    cudaGetSymbolAddress((void**)&w1, g_w1);
    cudaGetSymbolAddress((void**)&w2, g_w2);

    cudaFuncSetAttribute(band_attn_tc,
                         cudaFuncAttributeMaxDynamicSharedMemorySize, ATTN_SMEM);
    cudaFuncSetAttribute(gemm_f16<true,true>,
                         cudaFuncAttributeMaxDynamicSharedMemorySize, GEMM_SMEM);
    cudaFuncSetAttribute(gemm_f16<false,false>,
                         cudaFuncAttributeMaxDynamicSharedMemorySize, GEMM_SMEM);
    cudaFuncSetAttribute(gemm_qkv,
                         cudaFuncAttributeMaxDynamicSharedMemorySize, GEMM_SMEM);

    // weight transpose+convert to fp16 [N][K], batched over layers
    {
        dim3 blk(32, 8);
        trans_f16_kernel<<<dim3(DD/32, DD/32, LL), blk>>>(Wq, wq, DD, DD);
        trans_f16_kernel<<<dim3(DD/32, DD/32, LL), blk>>>(Wk, wk, DD, DD);
        trans_f16_kernel<<<dim3(DD/32, DD/32, LL), blk>>>(Wv, wv, DD, DD);
        trans_f16_kernel<<<dim3(DFF/32, DD/32, LL), blk>>>(W1, w1, DD, DFF);
        trans_f16_kernel<<<dim3(DD/32, DFF/32, LL), blk>>>(W2, w2, DFF, DD);
    }

    // src -> fp16 for layer-0 QKV
    f32_to_f16_kernel<<<(MM*DD/4 + 255)/256, 256>>>(src, xh, MM*DD/4);

    dim3 gQKV(9, MM/128);
    dim3 gF1(DFF/256, MM/128);
    dim3 gF2(DD/256, MM/128);
    dim3 gA(NC, HH, BB);

    for (int i = 0; i < LL; i++) {
        const float* xin = (i == 0) ? src : x;

        gemm_qkv<<<gQKV, 256, GEMM_SMEM>>>(xh,
            wq + (size_t)i*DD*DD, wk + (size_t)i*DD*DD, wv + (size_t)i*DD*DD,
            bq + i*DD, bk + i*DD, bv + i*DD, qh, kh, vh);

        band_attn_tc<<<gA, 256, ATTN_SMEM>>>(qh, kh, vh, xin, x, xh);

        gemm_f16<true,true><<<gF1, 256, GEMM_SMEM>>>(
            xh, w1 + (size_t)i*DD*DFF, b1 + i*DFF, nullptr, h1, DFF, DD);
        gemm_f16<false,false><<<gF2, 256, GEMM_SMEM>>>(
            h1, w2 + (size_t)i*DFF*DD, b2 + i*DD, h2, nullptr, DD, DFF);

        add_ln_kernel<<<MM, 256>>>(x, h2, ln2_g + i*DD, ln2_b + i*DD, x, xh, 1);
    }

    add_ln_kernel<<<MM, 256>>>(x, nullptr, lnf_g, lnf_b, (float*)d_out, nullptr, 0);
}